// round 4
// baseline (speedup 1.0000x reference)
#include <cuda_runtime.h>

// ---------------------------------------------------------------------------
// Neural-SDF ray march + tube-point min + reflectance MLP, fused per-ray.
//   out[i] = (hit ? rgb : 0, -100 * min_sdf_along_tube)
// Key facts used:
//   * tput == curr_min (the final sdf re-eval is at the exact argmin point)
//   * hits is sticky -> warp-level early break in the march loop
// Layer-2 (128x128) uses Blackwell packed fp32 FMA (fma.rn.f32x2) with the
// hidden vector pre-packed over k into 64 u64 registers and W2 staged in
// shared memory pair-interleaved as [k/2][j] (uniform/broadcast LDS.128).
// ---------------------------------------------------------------------------

namespace {
constexpr int   HN     = 128;
constexpr float kNEAR  = 0.2f;
constexpr float kFAR   = 2.0f;
constexpr float kALPHA = 100.0f;
constexpr float kEPS   = 0.005f;
constexpr int   kITERS = 32;
constexpr int   kTP    = 32;
// step = (FAR + 0.5*(2/32)) / 32 = 2.03125/32, exact in fp32
constexpr float kSTEP  = 0.0634765625f;

// float offsets inside dynamic shared memory
constexpr int OFF_W2   = 0;       // 16384 floats: pair-interleaved [k/2][j]{even,odd}
constexpr int OFF_W1   = 16384;   // 128 x float4: (W1[0][j], W1[1][j], W1[2][j], b1[j])
constexpr int OFF_B2   = 16896;   // 128
constexpr int OFF_W3   = 17024;   // 128
constexpr int OFF_R1A  = 17152;   // 128 x float4: R1 rows 0..3
constexpr int OFF_R1B  = 17664;   // 128 x float4: (R1[4][j], R1[5][j], rb1[j], 0)
constexpr int OFF_R2   = 18176;   // 128 x float4: (R2[j][0..2], 0)
constexpr int OFF_MISC = 18688;   // rb2[0..2], b3
constexpr int SMEM_FLOATS = 18692;
constexpr int SMEM_BYTES  = SMEM_FLOATS * 4;
}  // namespace

// SDF MLP: 3 -> 128 (relu) -> 128 (relu) -> 1   (bias b3 added by caller)
__device__ __noinline__ float sdf_eval(float x0, float x1, float x2) {
    extern __shared__ float smem[];
    const float4* sW1 = reinterpret_cast<const float4*>(smem + OFF_W1);
    const unsigned long long* sW2q =
        reinterpret_cast<const unsigned long long*>(smem + OFF_W2);
    const float4* sB2 = reinterpret_cast<const float4*>(smem + OFF_B2);
    const float4* sW3 = reinterpret_cast<const float4*>(smem + OFF_W3);

    // Layer 1: h1[j] = relu(W1^T x + b1), built pre-packed over k:
    // h1p[kp] = pack(h1[2kp], h1[2kp+1])
    unsigned long long h1p[HN / 2];
#pragma unroll
    for (int jp = 0; jp < HN / 2; ++jp) {
        float4 wa = sW1[2 * jp];
        float4 wb = sW1[2 * jp + 1];
        float he = fmaxf(fmaf(wa.x, x0, fmaf(wa.y, x1, fmaf(wa.z, x2, wa.w))), 0.0f);
        float ho = fmaxf(fmaf(wb.x, x0, fmaf(wb.y, x1, fmaf(wb.z, x2, wb.w))), 0.0f);
        asm("mov.b64 %0, {%1, %2};"
            : "=l"(h1p[jp])
            : "r"(__float_as_uint(he)), "r"(__float_as_uint(ho)));
    }

    // Layers 2+3 fused: out = sum_j relu(b2[j] + sum_k h1[k]*W2[k][j]) * W3[j]
    float out = 0.0f;
#pragma unroll 1
    for (int q = 0; q < HN / 4; ++q) {
        const unsigned long long* wrow = sW2q + q * 4;  // columns 4q..4q+3
        unsigned long long a0 = 0ull, a1 = 0ull, a2 = 0ull, a3 = 0ull;
#pragma unroll
        for (int kp = 0; kp < HN / 2; ++kp) {
            ulonglong2 wA = *reinterpret_cast<const ulonglong2*>(wrow + kp * HN);
            ulonglong2 wB = *reinterpret_cast<const ulonglong2*>(wrow + kp * HN + 2);
            unsigned long long h = h1p[kp];
            asm("fma.rn.f32x2 %0, %1, %2, %0;" : "+l"(a0) : "l"(h), "l"(wA.x));
            asm("fma.rn.f32x2 %0, %1, %2, %0;" : "+l"(a1) : "l"(h), "l"(wA.y));
            asm("fma.rn.f32x2 %0, %1, %2, %0;" : "+l"(a2) : "l"(h), "l"(wB.x));
            asm("fma.rn.f32x2 %0, %1, %2, %0;" : "+l"(a3) : "l"(h), "l"(wB.y));
        }
        float4 b2v = sB2[q];
        float4 w3v = sW3[q];
        unsigned lo, hi;
        float h2;
        asm("mov.b64 {%0,%1}, %2;" : "=r"(lo), "=r"(hi) : "l"(a0));
        h2 = fmaxf(__uint_as_float(lo) + __uint_as_float(hi) + b2v.x, 0.0f);
        out = fmaf(h2, w3v.x, out);
        asm("mov.b64 {%0,%1}, %2;" : "=r"(lo), "=r"(hi) : "l"(a1));
        h2 = fmaxf(__uint_as_float(lo) + __uint_as_float(hi) + b2v.y, 0.0f);
        out = fmaf(h2, w3v.y, out);
        asm("mov.b64 {%0,%1}, %2;" : "=r"(lo), "=r"(hi) : "l"(a2));
        h2 = fmaxf(__uint_as_float(lo) + __uint_as_float(hi) + b2v.z, 0.0f);
        out = fmaf(h2, w3v.z, out);
        asm("mov.b64 {%0,%1}, %2;" : "=r"(lo), "=r"(hi) : "l"(a3));
        h2 = fmaxf(__uint_as_float(lo) + __uint_as_float(hi) + b2v.w, 0.0f);
        out = fmaf(h2, w3v.w, out);
    }
    return out;
}

__global__ void __launch_bounds__(128) sdf_fused_kernel(
    const float* __restrict__ rays,
    const float* __restrict__ W1, const float* __restrict__ b1,
    const float* __restrict__ W2, const float* __restrict__ b2,
    const float* __restrict__ W3, const float* __restrict__ b3,
    const float* __restrict__ R1, const float* __restrict__ rb1,
    const float* __restrict__ R2, const float* __restrict__ rb2,
    float* __restrict__ out, int n)
{
    extern __shared__ float smem[];
    const int tid = threadIdx.x;

    // ---- stage weights into shared ----
    // W2 pair-interleaved over k: smem[2*(kp*128+j)] = W2[2kp][j] (lo),
    //                             smem[2*(kp*128+j)+1] = W2[2kp+1][j] (hi)
    for (int i = tid; i < HN * HN / 2; i += blockDim.x) {
        int kp = i >> 7;
        int j  = i & (HN - 1);
        smem[OFF_W2 + 2 * i]     = W2[(2 * kp) * HN + j];
        smem[OFF_W2 + 2 * i + 1] = W2[(2 * kp + 1) * HN + j];
    }
    {
        float4* w1v  = reinterpret_cast<float4*>(smem + OFF_W1);
        float4* r1av = reinterpret_cast<float4*>(smem + OFF_R1A);
        float4* r1bv = reinterpret_cast<float4*>(smem + OFF_R1B);
        float4* r2v  = reinterpret_cast<float4*>(smem + OFF_R2);
        for (int j = tid; j < HN; j += blockDim.x) {
            w1v[j]  = make_float4(W1[j], W1[HN + j], W1[2 * HN + j], b1[j]);
            smem[OFF_B2 + j] = b2[j];
            smem[OFF_W3 + j] = W3[j];
            r1av[j] = make_float4(R1[j], R1[HN + j], R1[2 * HN + j], R1[3 * HN + j]);
            r1bv[j] = make_float4(R1[4 * HN + j], R1[5 * HN + j], rb1[j], 0.0f);
            r2v[j]  = make_float4(R2[3 * j], R2[3 * j + 1], R2[3 * j + 2], 0.0f);
        }
    }
    if (tid < 3) smem[OFF_MISC + tid] = rb2[tid];
    if (tid == 0) smem[OFF_MISC + 3] = b3[0];
    __syncthreads();

    int ray = blockIdx.x * blockDim.x + tid;
    const bool active = ray < n;
    if (!active) ray = n - 1;  // keep warp convergent; store is predicated

    const float ro0 = rays[ray * 6 + 0];
    const float ro1 = rays[ray * 6 + 1];
    const float ro2 = rays[ray * 6 + 2];
    const float rd0 = rays[ray * 6 + 3];
    const float rd1 = rays[ray * 6 + 4];
    const float rd2 = rays[ray * 6 + 5];
    const float bb3 = smem[OFF_MISC + 3];

    // ---- sphere tracing (hits is sticky -> warp-level early break) ----
    float cd = kNEAR;
    bool hit = false;
#pragma unroll 1
    for (int it = 0; it < kITERS; ++it) {
        float x0 = __fadd_rn(ro0, __fmul_rn(rd0, cd));
        float x1 = __fadd_rn(ro1, __fmul_rn(rd1, cd));
        float x2 = __fadd_rn(ro2, __fmul_rn(rd2, cd));
        float dist = sdf_eval(x0, x1, x2) + bb3;
        bool h = (dist < kEPS) && (cd >= kNEAR) && (cd <= kFAR);
        hit = hit || h;
        if (!hit) cd += dist;
        if (__all_sync(0xffffffffu, hit)) break;
    }

    // ---- reflectance MLP at pts = ro + rd*cd ----
    float p0 = __fadd_rn(ro0, __fmul_rn(rd0, cd));
    float p1 = __fadd_rn(ro1, __fmul_rn(rd1, cd));
    float p2 = __fadd_rn(ro2, __fmul_rn(rd2, cd));
    float rgb0 = smem[OFF_MISC + 0];
    float rgb1 = smem[OFF_MISC + 1];
    float rgb2 = smem[OFF_MISC + 2];
    {
        const float4* r1a = reinterpret_cast<const float4*>(smem + OFF_R1A);
        const float4* r1b = reinterpret_cast<const float4*>(smem + OFF_R1B);
        const float4* r2v = reinterpret_cast<const float4*>(smem + OFF_R2);
#pragma unroll 4
        for (int j = 0; j < HN; ++j) {
            float4 a = r1a[j];
            float4 b = r1b[j];
            float hv = fmaf(a.x, p0,
                       fmaf(a.y, p1,
                       fmaf(a.z, p2,
                       fmaf(a.w, rd0,
                       fmaf(b.x, rd1,
                       fmaf(b.y, rd2, b.z))))));
            hv = fmaxf(hv, 0.0f);
            float4 w = r2v[j];
            rgb0 = fmaf(hv, w.x, rgb0);
            rgb1 = fmaf(hv, w.y, rgb1);
            rgb2 = fmaf(hv, w.z, rgb2);
        }
    }
    if (!hit) { rgb0 = 0.0f; rgb1 = 0.0f; rgb2 = 0.0f; }

    // ---- tube-point min; tput == curr_min (recomputation is bit-identical) ----
    float m = sdf_eval(ro0, ro1, ro2) + bb3;  // sd0 at t = 0
#pragma unroll 1
    for (int i = 1; i <= kTP; ++i) {
        float t = kSTEP * (float)i;  // exact: step*(i+1) in the reference
        float x0 = __fadd_rn(ro0, __fmul_rn(rd0, t));
        float x1 = __fadd_rn(ro1, __fmul_rn(rd1, t));
        float x2 = __fadd_rn(ro2, __fmul_rn(rd2, t));
        float sd = sdf_eval(x0, x1, x2) + bb3;
        m = fminf(m, sd);
    }

    if (active) {
        float4 o;
        o.x = rgb0;
        o.y = rgb1;
        o.z = rgb2;
        o.w = -kALPHA * m;
        reinterpret_cast<float4*>(out)[ray] = o;
    }
}

extern "C" void kernel_launch(void* const* d_in, const int* in_sizes, int n_in,
                              void* d_out, int out_size) {
    const float* rays = (const float*)d_in[0];
    const float* W1   = (const float*)d_in[1];
    const float* b1   = (const float*)d_in[2];
    const float* W2   = (const float*)d_in[3];
    const float* b2   = (const float*)d_in[4];
    const float* W3   = (const float*)d_in[5];
    const float* b3   = (const float*)d_in[6];
    const float* R1   = (const float*)d_in[7];
    const float* rb1  = (const float*)d_in[8];
    const float* R2   = (const float*)d_in[9];
    const float* rb2  = (const float*)d_in[10];
    float* out = (float*)d_out;

    const int n = in_sizes[0] / 6;  // number of rays (1<<20)

    cudaFuncSetAttribute(sdf_fused_kernel,
                         cudaFuncAttributeMaxDynamicSharedMemorySize, SMEM_BYTES);

    const int block = 128;
    const int grid = (n + block - 1) / block;
    sdf_fused_kernel<<<grid, block, SMEM_BYTES>>>(
        rays, W1, b1, W2, b2, W3, b3, R1, rb1, R2, rb2, out, n);
}

// round 6
// speedup vs baseline: 2.6140x; 2.6140x over previous
#include <cuda_runtime.h>
#include <cstdint>

// ---------------------------------------------------------------------------
// Neural-SDF ray march + tube min + reflectance.
// Warp-cooperative: 32 rays/warp; each SDF eval = 32x128x128 GEMM on the
// legacy tensor pipe via mma.sync.m16n8k8 tf32, 3-term error compensation
// (Ahi*Bhi + Alo*Bhi + Ahi*Blo) for ~fp32 accuracy.
//   * A (h1) computed directly in mma fragment layout (never staged in SMEM)
//   * B (W2 hi/lo) pre-packed in fragment order: 1 LDS.128 feeds 6 mma
//   * tput == curr_min identity removes the final SDF re-eval
// ---------------------------------------------------------------------------

#define DINL __device__ __forceinline__

namespace {
constexpr int   HN     = 128;
constexpr float kNEAR  = 0.2f;
constexpr float kFAR   = 2.0f;
constexpr float kALPHA = 100.0f;
constexpr float kEPS   = 0.005f;
constexpr int   kITERS = 32;
constexpr int   kTP    = 32;
constexpr float kSTEP  = 0.0634765625f;  // (2 + 0.5*(2/32))/32, exact fp32
constexpr uint32_t TF32_MASK = 0xFFFFE000u;

// shared memory layout (float offsets)
constexpr int OFF_B    = 0;        // 32768 floats: W2 hi/lo frag-packed
constexpr int OFF_W1   = 32768;    // float4[128]: (W1[0][k],W1[1][k],W1[2][k],b1[k])
constexpr int OFF_BW   = 33280;    // float2[128]: (b2[n], W3[n])
constexpr int OFF_R1A  = 33536;    // float4[128]: R1 rows 0..3
constexpr int OFF_R1B  = 34048;    // float4[128]: (R1[4][j],R1[5][j],rb1[j],0)
constexpr int OFF_R2   = 34560;    // float4[128]: (R2[j][0..2],0)
constexpr int OFF_MISC = 35072;    // rb2[0..2], b3
constexpr int SMEM_FLOATS = 35076;
constexpr int SMEM_BYTES  = SMEM_FLOATS * 4;
}  // namespace

// ----------------------------- mma wrappers ---------------------------------
DINL void mma_acc(float c[4], uint32_t a0, uint32_t a1, uint32_t a2, uint32_t a3,
                  uint32_t b0, uint32_t b1) {
    asm volatile(
        "mma.sync.aligned.m16n8k8.row.col.f32.tf32.tf32.f32 "
        "{%0,%1,%2,%3},{%4,%5,%6,%7},{%8,%9},{%0,%1,%2,%3};"
        : "+f"(c[0]), "+f"(c[1]), "+f"(c[2]), "+f"(c[3])
        : "r"(a0), "r"(a1), "r"(a2), "r"(a3), "r"(b0), "r"(b1));
}
DINL void mma_zero(float c[4], uint32_t a0, uint32_t a1, uint32_t a2, uint32_t a3,
                   uint32_t b0, uint32_t b1) {
    float z = 0.0f;
    asm volatile(
        "mma.sync.aligned.m16n8k8.row.col.f32.tf32.tf32.f32 "
        "{%0,%1,%2,%3},{%4,%5,%6,%7},{%8,%9},{%10,%10,%10,%10};"
        : "=f"(c[0]), "=f"(c[1]), "=f"(c[2]), "=f"(c[3])
        : "r"(a0), "r"(a1), "r"(a2), "r"(a3), "r"(b0), "r"(b1), "f"(z));
}

// one k-chunk worth of mma over all 16 n-blocks
template <bool FIRST>
DINL void kc_body(float C[2][16][4], const float4* __restrict__ bk,
                  const uint32_t* ahi, const uint32_t* alo) {
#pragma unroll
    for (int nb = 0; nb < 16; ++nb) {
        float4 B = bk[nb * 32];
        uint32_t bh0 = __float_as_uint(B.x), bh1 = __float_as_uint(B.y);
        uint32_t bl0 = __float_as_uint(B.z), bl1 = __float_as_uint(B.w);
        if (FIRST) {
            mma_zero(C[0][nb], ahi[0], ahi[1], ahi[2], ahi[3], bh0, bh1);
            mma_zero(C[1][nb], ahi[4], ahi[5], ahi[6], ahi[7], bh0, bh1);
        } else {
            mma_acc(C[0][nb], ahi[0], ahi[1], ahi[2], ahi[3], bh0, bh1);
            mma_acc(C[1][nb], ahi[4], ahi[5], ahi[6], ahi[7], bh0, bh1);
        }
        mma_acc(C[0][nb], alo[0], alo[1], alo[2], alo[3], bh0, bh1);
        mma_acc(C[1][nb], alo[4], alo[5], alo[6], alo[7], bh0, bh1);
        mma_acc(C[0][nb], ahi[0], ahi[1], ahi[2], ahi[3], bl0, bl1);
        mma_acc(C[1][nb], ahi[4], ahi[5], ahi[6], ahi[7], bl0, bl1);
    }
}

// layer-1 in fragment layout: lane's 8 A-slots for k-chunk kc
DINL void compute_A(int kc, int c4, const float* X0, const float* X1,
                    const float* X2, const float4* __restrict__ w1pack,
                    uint32_t ahi[8], uint32_t alo[8]) {
    float4 wA = w1pack[kc * 8 + c4];
    float4 wB = w1pack[kc * 8 + c4 + 4];
#pragma unroll
    for (int c = 0; c < 4; ++c) {
        float hA = fmaxf(fmaf(wA.x, X0[c], fmaf(wA.y, X1[c], fmaf(wA.z, X2[c], wA.w))), 0.0f);
        float hB = fmaxf(fmaf(wB.x, X0[c], fmaf(wB.y, X1[c], fmaf(wB.z, X2[c], wB.w))), 0.0f);
        uint32_t hiA = __float_as_uint(hA) & TF32_MASK;
        uint32_t loA = __float_as_uint(hA - __uint_as_float(hiA)) & TF32_MASK;
        uint32_t hiB = __float_as_uint(hB) & TF32_MASK;
        uint32_t loB = __float_as_uint(hB - __uint_as_float(hiB)) & TF32_MASK;
        int t = c >> 1, rr = c & 1;   // c -> ray (l>>2)+8c: tile t slot rr / rr+2... wait
        // slots per tile: {a0,a1,a2,a3} = {h(kA,ray g+16t), h(kA,ray g+8+16t),
        //                                  h(kB,ray g+16t), h(kB,ray g+8+16t)}
        ahi[t * 4 + rr]     = hiA;
        ahi[t * 4 + 2 + rr] = hiB;
        alo[t * 4 + rr]     = loA;
        alo[t * 4 + 2 + rr] = loB;
    }
}

// full SDF eval for the warp's 32 rays; returns this lane's own-ray value
// (WITHOUT b3). X*[c] = coords of local ray (lane>>2) + 8c.
DINL float sdf_eval_warp(const float* X0, const float* X1, const float* X2,
                         const float4* __restrict__ w1pack,
                         const float4* __restrict__ sB4,
                         const float4* __restrict__ bwv, int lane) {
    const int c4 = lane & 3;
    float C[2][16][4];
    const float4* bp = sB4 + lane;

    {   // kc = 0 (initializes C)
        uint32_t ahi[8], alo[8];
        compute_A(0, c4, X0, X1, X2, w1pack, ahi, alo);
        kc_body<true>(C, bp, ahi, alo);
    }
#pragma unroll 1
    for (int kc = 1; kc < 16; ++kc) {
        uint32_t ahi[8], alo[8];
        compute_A(kc, c4, X0, X1, X2, w1pack, ahi, alo);
        kc_body<false>(C, bp + kc * 512, ahi, alo);
    }

    // epilogue: p[r] = sum_n relu(C(r,n)+b2[n])*W3[n], 4 rays per lane
    float p0 = 0.f, p1 = 0.f, p2 = 0.f, p3 = 0.f;
#pragma unroll
    for (int nb = 0; nb < 16; ++nb) {
        float4 bw = bwv[nb * 4 + c4];  // (b2[n],W3[n],b2[n+1],W3[n+1])
        p0 = fmaf(fmaxf(C[0][nb][0] + bw.x, 0.f), bw.y, p0);
        p0 = fmaf(fmaxf(C[0][nb][1] + bw.z, 0.f), bw.w, p0);
        p1 = fmaf(fmaxf(C[0][nb][2] + bw.x, 0.f), bw.y, p1);
        p1 = fmaf(fmaxf(C[0][nb][3] + bw.z, 0.f), bw.w, p1);
        p2 = fmaf(fmaxf(C[1][nb][0] + bw.x, 0.f), bw.y, p2);
        p2 = fmaf(fmaxf(C[1][nb][1] + bw.z, 0.f), bw.w, p2);
        p3 = fmaf(fmaxf(C[1][nb][2] + bw.x, 0.f), bw.y, p3);
        p3 = fmaf(fmaxf(C[1][nb][3] + bw.z, 0.f), bw.w, p3);
    }
    // reduce across the 4 lanes of each group (same l>>2)
    p0 += __shfl_xor_sync(0xffffffffu, p0, 1);
    p0 += __shfl_xor_sync(0xffffffffu, p0, 2);
    p1 += __shfl_xor_sync(0xffffffffu, p1, 1);
    p1 += __shfl_xor_sync(0xffffffffu, p1, 2);
    p2 += __shfl_xor_sync(0xffffffffu, p2, 1);
    p2 += __shfl_xor_sync(0xffffffffu, p2, 2);
    p3 += __shfl_xor_sync(0xffffffffu, p3, 1);
    p3 += __shfl_xor_sync(0xffffffffu, p3, 2);
    // lane 4g+c exposes ray g+8c; owner lane l fetches from 4*(l&7)+(l>>3)
    float expose = (c4 == 0) ? p0 : (c4 == 1) ? p1 : (c4 == 2) ? p2 : p3;
    int src = ((lane & 7) << 2) | (lane >> 3);
    return __shfl_sync(0xffffffffu, expose, src);
}

// broadcast own coords to fragment-ray slots
DINL void bcast_X(float x0, float x1, float x2, int lane,
                  float* X0, float* X1, float* X2) {
#pragma unroll
    for (int c = 0; c < 4; ++c) {
        int src = (lane >> 2) + 8 * c;
        X0[c] = __shfl_sync(0xffffffffu, x0, src);
        X1[c] = __shfl_sync(0xffffffffu, x1, src);
        X2[c] = __shfl_sync(0xffffffffu, x2, src);
    }
}

// ------------------------------- kernel -------------------------------------
__global__ void __launch_bounds__(256, 1) sdf_mma_kernel(
    const float* __restrict__ rays,
    const float* __restrict__ W1, const float* __restrict__ b1,
    const float* __restrict__ W2, const float* __restrict__ b2,
    const float* __restrict__ W3, const float* __restrict__ b3,
    const float* __restrict__ R1, const float* __restrict__ rb1,
    const float* __restrict__ R2, const float* __restrict__ rb2,
    float* __restrict__ out, int n)
{
    extern __shared__ float smem[];
    const int tid = threadIdx.x;
    const int lane = tid & 31;

    // ---- stage B = W2 hi/lo in mma-fragment pack ----
    // float4 at [(kc*16+nb)*32 + l] = (bhi[k0][n], bhi[k0+4][n], blo[k0][n], blo[k0+4][n])
    // with k0 = kc*8+(l&3), n = nb*8+(l>>2)
    for (int idx = tid; idx < HN * HN; idx += blockDim.x) {
        int k = idx >> 7, nn = idx & (HN - 1);
        float w = W2[idx];  // W2[k][n]
        uint32_t hi = __float_as_uint(w) & TF32_MASK;
        uint32_t lo = __float_as_uint(w - __uint_as_float(hi)) & TF32_MASK;
        int kc = k >> 3, kk = k & 7, c = kk & 3, half = kk >> 2;
        int l = ((nn & 7) << 2) | c;
        int fb = (kc * 16 + (nn >> 3)) * 32 + l;
        smem[OFF_B + fb * 4 + half]     = __uint_as_float(hi);
        smem[OFF_B + fb * 4 + 2 + half] = __uint_as_float(lo);
    }
    // ---- small weights ----
    {
        float4* w1v  = reinterpret_cast<float4*>(smem + OFF_W1);
        float2* bwv2 = reinterpret_cast<float2*>(smem + OFF_BW);
        float4* r1av = reinterpret_cast<float4*>(smem + OFF_R1A);
        float4* r1bv = reinterpret_cast<float4*>(smem + OFF_R1B);
        float4* r2v  = reinterpret_cast<float4*>(smem + OFF_R2);
        for (int j = tid; j < HN; j += blockDim.x) {
            w1v[j]  = make_float4(W1[j], W1[HN + j], W1[2 * HN + j], b1[j]);
            bwv2[j] = make_float2(b2[j], W3[j]);
            r1av[j] = make_float4(R1[j], R1[HN + j], R1[2 * HN + j], R1[3 * HN + j]);
            r1bv[j] = make_float4(R1[4 * HN + j], R1[5 * HN + j], rb1[j], 0.0f);
            r2v[j]  = make_float4(R2[3 * j], R2[3 * j + 1], R2[3 * j + 2], 0.0f);
        }
    }
    if (tid < 3) smem[OFF_MISC + tid] = rb2[tid];
    if (tid == 0) smem[OFF_MISC + 3] = b3[0];
    __syncthreads();

    const float4* w1pack = reinterpret_cast<const float4*>(smem + OFF_W1);
    const float4* sB4    = reinterpret_cast<const float4*>(smem + OFF_B);
    const float4* bwv    = reinterpret_cast<const float4*>(smem + OFF_BW);
    const float bb3 = smem[OFF_MISC + 3];

    int ray = blockIdx.x * blockDim.x + tid;
    const bool active = ray < n;
    if (!active) ray = n - 1;
    const float ro0 = rays[ray * 6 + 0], ro1 = rays[ray * 6 + 1], ro2 = rays[ray * 6 + 2];
    const float rd0 = rays[ray * 6 + 3], rd1 = rays[ray * 6 + 4], rd2 = rays[ray * 6 + 5];

    // ============ sphere tracing (warp-wide early break) ============
    float cd = kNEAR;
    bool hit = false;
#pragma unroll 1
    for (int it = 0; it < kITERS; ++it) {
        float x0 = __fadd_rn(ro0, __fmul_rn(rd0, cd));
        float x1 = __fadd_rn(ro1, __fmul_rn(rd1, cd));
        float x2 = __fadd_rn(ro2, __fmul_rn(rd2, cd));
        float X0[4], X1[4], X2[4];
        bcast_X(x0, x1, x2, lane, X0, X1, X2);
        float dist = sdf_eval_warp(X0, X1, X2, w1pack, sB4, bwv, lane) + bb3;
        bool h = (dist < kEPS) && (cd >= kNEAR) && (cd <= kFAR);
        hit = hit || h;
        if (!hit) cd += dist;
        if (__all_sync(0xffffffffu, hit)) break;
    }

    // ============ reflectance MLP (scalar, cheap) ============
    float p0 = __fadd_rn(ro0, __fmul_rn(rd0, cd));
    float p1 = __fadd_rn(ro1, __fmul_rn(rd1, cd));
    float p2 = __fadd_rn(ro2, __fmul_rn(rd2, cd));
    float rgb0 = smem[OFF_MISC + 0], rgb1 = smem[OFF_MISC + 1], rgb2 = smem[OFF_MISC + 2];
    {
        const float4* r1a = reinterpret_cast<const float4*>(smem + OFF_R1A);
        const float4* r1b = reinterpret_cast<const float4*>(smem + OFF_R1B);
        const float4* r2v = reinterpret_cast<const float4*>(smem + OFF_R2);
#pragma unroll 4
        for (int j = 0; j < HN; ++j) {
            float4 a = r1a[j];
            float4 b = r1b[j];
            float hv = fmaf(a.x, p0, fmaf(a.y, p1, fmaf(a.z, p2,
                       fmaf(a.w, rd0, fmaf(b.x, rd1, fmaf(b.y, rd2, b.z))))));
            hv = fmaxf(hv, 0.0f);
            float4 w = r2v[j];
            rgb0 = fmaf(hv, w.x, rgb0);
            rgb1 = fmaf(hv, w.y, rgb1);
            rgb2 = fmaf(hv, w.z, rgb2);
        }
    }
    if (!hit) { rgb0 = 0.0f; rgb1 = 0.0f; rgb2 = 0.0f; }

    // ============ tube-point min; tput == curr_min ============
    float m;
    {   // i = 0: point is exactly ro
        float X0[4], X1[4], X2[4];
        bcast_X(ro0, ro1, ro2, lane, X0, X1, X2);
        m = sdf_eval_warp(X0, X1, X2, w1pack, sB4, bwv, lane) + bb3;
    }
#pragma unroll 1
    for (int i = 1; i <= kTP; ++i) {
        float t = kSTEP * (float)i;  // == reference step*(i+1)
        float x0 = __fadd_rn(ro0, __fmul_rn(rd0, t));
        float x1 = __fadd_rn(ro1, __fmul_rn(rd1, t));
        float x2 = __fadd_rn(ro2, __fmul_rn(rd2, t));
        float X0[4], X1[4], X2[4];
        bcast_X(x0, x1, x2, lane, X0, X1, X2);
        float sd = sdf_eval_warp(X0, X1, X2, w1pack, sB4, bwv, lane) + bb3;
        m = fminf(m, sd);
    }

    if (active) {
        float4 o;
        o.x = rgb0; o.y = rgb1; o.z = rgb2; o.w = -kALPHA * m;
        reinterpret_cast<float4*>(out)[ray] = o;
    }
}

extern "C" void kernel_launch(void* const* d_in, const int* in_sizes, int n_in,
                              void* d_out, int out_size) {
    const float* rays = (const float*)d_in[0];
    const float* W1   = (const float*)d_in[1];
    const float* b1   = (const float*)d_in[2];
    const float* W2   = (const float*)d_in[3];
    const float* b2   = (const float*)d_in[4];
    const float* W3   = (const float*)d_in[5];
    const float* b3   = (const float*)d_in[6];
    const float* R1   = (const float*)d_in[7];
    const float* rb1  = (const float*)d_in[8];
    const float* R2   = (const float*)d_in[9];
    const float* rb2  = (const float*)d_in[10];
    float* out = (float*)d_out;

    const int n = in_sizes[0] / 6;

    cudaFuncSetAttribute(sdf_mma_kernel,
                         cudaFuncAttributeMaxDynamicSharedMemorySize, SMEM_BYTES);

    const int block = 256;
    const int grid = (n + block - 1) / block;
    sdf_mma_kernel<<<grid, block, SMEM_BYTES>>>(
        rays, W1, b1, W2, b2, W3, b3, R1, rb1, R2, rb2, out, n);
}

// round 7
// speedup vs baseline: 4.7276x; 1.8086x over previous
#include <cuda_runtime.h>
#include <cstdint>

// ---------------------------------------------------------------------------
// Neural-SDF ray march + tube min + reflectance.
// Warp-cooperative: 32 rays/warp; each SDF eval = 32x128x128 GEMM via
// mma.sync.m16n8k16 bf16 with 3-term error compensation:
//     D = Ahi*Bhi + Alo*Bhi + Ahi*Blo   (error ~2^-16, fp32-grade for 1e-3 tol)
//   * A (h1) computed directly in mma fragment layout (never staged in SMEM)
//   * B (W2 hi/lo) pre-packed in fragment order: 1 LDS.128 feeds 6 mma
//   * tput == curr_min identity removes the final SDF re-eval
// ---------------------------------------------------------------------------

#define DINL __device__ __forceinline__

namespace {
constexpr int   HN     = 128;
constexpr float kNEAR  = 0.2f;
constexpr float kFAR   = 2.0f;
constexpr float kALPHA = 100.0f;
constexpr float kEPS   = 0.005f;
constexpr int   kITERS = 32;
constexpr int   kTP    = 32;
constexpr float kSTEP  = 0.0634765625f;  // (2 + 0.5*(2/32))/32, exact fp32

// shared memory layout (float offsets)
constexpr int OFF_B    = 0;        // 16384 floats: W2 bf16 hi/lo frag-packed
constexpr int OFF_W1   = 16384;    // float4[128]: (W1[0][k],W1[1][k],W1[2][k],b1[k])
constexpr int OFF_BW   = 16896;    // float2[128]: (b2[n], W3[n])
constexpr int OFF_R1A  = 17152;    // float4[128]: R1 rows 0..3
constexpr int OFF_R1B  = 17664;    // float4[128]: (R1[4][j],R1[5][j],rb1[j],0)
constexpr int OFF_R2   = 18176;    // float4[128]: (R2[j][0..2],0)
constexpr int OFF_MISC = 18688;    // rb2[0..2], b3
constexpr int SMEM_FLOATS = 18692;
constexpr int SMEM_BYTES  = SMEM_FLOATS * 4;
}  // namespace

// ----------------------------- helpers --------------------------------------
// bf16 truncation pack: low half = trunc_bf16(e0), high half = trunc_bf16(e1)
DINL uint32_t pack_trunc(float e0, float e1) {
    return __byte_perm(__float_as_uint(e0), __float_as_uint(e1), 0x7632);
}
// bf16 round-to-nearest pack: low = rn(e0), high = rn(e1)
DINL uint32_t pack_rn(float e0, float e1) {
    uint32_t d;
    asm("cvt.rn.bf16x2.f32 %0, %1, %2;" : "=r"(d) : "f"(e1), "f"(e0));
    return d;
}
DINL float trunc_bf16_f(float x) {
    return __uint_as_float(__float_as_uint(x) & 0xFFFF0000u);
}

// ----------------------------- mma wrappers ---------------------------------
DINL void mma_acc(float c[4], uint32_t a0, uint32_t a1, uint32_t a2, uint32_t a3,
                  uint32_t b0, uint32_t b1) {
    asm volatile(
        "mma.sync.aligned.m16n8k16.row.col.f32.bf16.bf16.f32 "
        "{%0,%1,%2,%3},{%4,%5,%6,%7},{%8,%9},{%0,%1,%2,%3};"
        : "+f"(c[0]), "+f"(c[1]), "+f"(c[2]), "+f"(c[3])
        : "r"(a0), "r"(a1), "r"(a2), "r"(a3), "r"(b0), "r"(b1));
}
DINL void mma_zero(float c[4], uint32_t a0, uint32_t a1, uint32_t a2, uint32_t a3,
                   uint32_t b0, uint32_t b1) {
    float z = 0.0f;
    asm volatile(
        "mma.sync.aligned.m16n8k16.row.col.f32.bf16.bf16.f32 "
        "{%0,%1,%2,%3},{%4,%5,%6,%7},{%8,%9},{%10,%10,%10,%10};"
        : "=f"(c[0]), "=f"(c[1]), "=f"(c[2]), "=f"(c[3])
        : "r"(a0), "r"(a1), "r"(a2), "r"(a3), "r"(b0), "r"(b1), "f"(z));
}

// one k16-chunk of mma over all 16 n-blocks
template <bool FIRST>
DINL void kc_body(float C[2][16][4], const float4* __restrict__ bk,
                  const uint32_t* ahi, const uint32_t* alo) {
#pragma unroll
    for (int nb = 0; nb < 16; ++nb) {
        float4 B = bk[nb * 32];
        uint32_t bh0 = __float_as_uint(B.x), bh1 = __float_as_uint(B.y);
        uint32_t bl0 = __float_as_uint(B.z), bl1 = __float_as_uint(B.w);
        if (FIRST) {
            mma_zero(C[0][nb], ahi[0], ahi[1], ahi[2], ahi[3], bh0, bh1);
            mma_zero(C[1][nb], ahi[4], ahi[5], ahi[6], ahi[7], bh0, bh1);
        } else {
            mma_acc(C[0][nb], ahi[0], ahi[1], ahi[2], ahi[3], bh0, bh1);
            mma_acc(C[1][nb], ahi[4], ahi[5], ahi[6], ahi[7], bh0, bh1);
        }
        mma_acc(C[0][nb], alo[0], alo[1], alo[2], alo[3], bh0, bh1);
        mma_acc(C[1][nb], alo[4], alo[5], alo[6], alo[7], bh0, bh1);
        mma_acc(C[0][nb], ahi[0], ahi[1], ahi[2], ahi[3], bl0, bl1);
        mma_acc(C[1][nb], ahi[4], ahi[5], ahi[6], ahi[7], bl0, bl1);
    }
}

// layer-1 in fragment layout for k16-chunk kc: lane owns k = 16kc+2t{,+1,+8,+9}
// and rays X[c] = warp-ray (lane>>2)+8c.
// A regs per m-tile mt: a0=(row g: k0,k0+1) a1=(row g+8: k0,k0+1)
//                       a2=(row g: k0+8,k0+9) a3=(row g+8: k0+8,k0+9)
// tile mt rows (g, g+8) are rays X[2mt], X[2mt+1].
DINL void compute_A(int kc, int t4, const float* X0, const float* X1,
                    const float* X2, const float4* __restrict__ w1pack,
                    uint32_t ahi[8], uint32_t alo[8]) {
    const int k0 = kc * 16 + 2 * t4;
    float4 w0 = w1pack[k0];
    float4 w1 = w1pack[k0 + 1];
    float4 w8 = w1pack[k0 + 8];
    float4 w9 = w1pack[k0 + 9];
    float h[4][4], lo[4][4];  // [kslot 0,1,8,9][ray c]
#pragma unroll
    for (int c = 0; c < 4; ++c) {
        h[0][c] = fmaxf(fmaf(w0.x, X0[c], fmaf(w0.y, X1[c], fmaf(w0.z, X2[c], w0.w))), 0.0f);
        h[1][c] = fmaxf(fmaf(w1.x, X0[c], fmaf(w1.y, X1[c], fmaf(w1.z, X2[c], w1.w))), 0.0f);
        h[2][c] = fmaxf(fmaf(w8.x, X0[c], fmaf(w8.y, X1[c], fmaf(w8.z, X2[c], w8.w))), 0.0f);
        h[3][c] = fmaxf(fmaf(w9.x, X0[c], fmaf(w9.y, X1[c], fmaf(w9.z, X2[c], w9.w))), 0.0f);
#pragma unroll
        for (int s = 0; s < 4; ++s) lo[s][c] = h[s][c] - trunc_bf16_f(h[s][c]);
    }
#pragma unroll
    for (int mt = 0; mt < 2; ++mt) {
        const int cA = 2 * mt, cB = 2 * mt + 1;
        ahi[mt * 4 + 0] = pack_trunc(h[0][cA], h[1][cA]);
        ahi[mt * 4 + 1] = pack_trunc(h[0][cB], h[1][cB]);
        ahi[mt * 4 + 2] = pack_trunc(h[2][cA], h[3][cA]);
        ahi[mt * 4 + 3] = pack_trunc(h[2][cB], h[3][cB]);
        alo[mt * 4 + 0] = pack_rn(lo[0][cA], lo[1][cA]);
        alo[mt * 4 + 1] = pack_rn(lo[0][cB], lo[1][cB]);
        alo[mt * 4 + 2] = pack_rn(lo[2][cA], lo[3][cA]);
        alo[mt * 4 + 3] = pack_rn(lo[2][cB], lo[3][cB]);
    }
}

// full SDF eval for the warp's 32 rays; returns this lane's own-ray value
// (WITHOUT b3). X*[c] = coords of warp-ray (lane>>2) + 8c.
DINL float sdf_eval_warp(const float* X0, const float* X1, const float* X2,
                         const float4* __restrict__ w1pack,
                         const float4* __restrict__ sB4,
                         const float4* __restrict__ bwv, int lane) {
    const int t4 = lane & 3;
    float C[2][16][4];
    const float4* bp = sB4 + lane;

    {
        uint32_t ahi[8], alo[8];
        compute_A(0, t4, X0, X1, X2, w1pack, ahi, alo);
        kc_body<true>(C, bp, ahi, alo);
    }
#pragma unroll 1
    for (int kc = 1; kc < 8; ++kc) {
        uint32_t ahi[8], alo[8];
        compute_A(kc, t4, X0, X1, X2, w1pack, ahi, alo);
        kc_body<false>(C, bp + kc * 512, ahi, alo);
    }

    // epilogue: p[r] = sum_n relu(C(r,n)+b2[n])*W3[n], 4 rays per lane
    float p0 = 0.f, p1 = 0.f, p2 = 0.f, p3 = 0.f;
#pragma unroll
    for (int nb = 0; nb < 16; ++nb) {
        float4 bw = bwv[nb * 4 + t4];  // (b2[n],W3[n],b2[n+1],W3[n+1]), n=8nb+2t
        p0 = fmaf(fmaxf(C[0][nb][0] + bw.x, 0.f), bw.y, p0);
        p0 = fmaf(fmaxf(C[0][nb][1] + bw.z, 0.f), bw.w, p0);
        p1 = fmaf(fmaxf(C[0][nb][2] + bw.x, 0.f), bw.y, p1);
        p1 = fmaf(fmaxf(C[0][nb][3] + bw.z, 0.f), bw.w, p1);
        p2 = fmaf(fmaxf(C[1][nb][0] + bw.x, 0.f), bw.y, p2);
        p2 = fmaf(fmaxf(C[1][nb][1] + bw.z, 0.f), bw.w, p2);
        p3 = fmaf(fmaxf(C[1][nb][2] + bw.x, 0.f), bw.y, p3);
        p3 = fmaf(fmaxf(C[1][nb][3] + bw.z, 0.f), bw.w, p3);
    }
    p0 += __shfl_xor_sync(0xffffffffu, p0, 1);
    p0 += __shfl_xor_sync(0xffffffffu, p0, 2);
    p1 += __shfl_xor_sync(0xffffffffu, p1, 1);
    p1 += __shfl_xor_sync(0xffffffffu, p1, 2);
    p2 += __shfl_xor_sync(0xffffffffu, p2, 1);
    p2 += __shfl_xor_sync(0xffffffffu, p2, 2);
    p3 += __shfl_xor_sync(0xffffffffu, p3, 1);
    p3 += __shfl_xor_sync(0xffffffffu, p3, 2);
    // lane 4g+c exposes ray g+8c; owner lane l fetches from 4*(l&7)+(l>>3)
    float expose = (t4 == 0) ? p0 : (t4 == 1) ? p1 : (t4 == 2) ? p2 : p3;
    int src = ((lane & 7) << 2) | (lane >> 3);
    return __shfl_sync(0xffffffffu, expose, src);
}

DINL void bcast_X(float x0, float x1, float x2, int lane,
                  float* X0, float* X1, float* X2) {
#pragma unroll
    for (int c = 0; c < 4; ++c) {
        int src = (lane >> 2) + 8 * c;
        X0[c] = __shfl_sync(0xffffffffu, x0, src);
        X1[c] = __shfl_sync(0xffffffffu, x1, src);
        X2[c] = __shfl_sync(0xffffffffu, x2, src);
    }
}

// ------------------------------- kernel -------------------------------------
__global__ void __launch_bounds__(256, 1) sdf_mma_kernel(
    const float* __restrict__ rays,
    const float* __restrict__ W1, const float* __restrict__ b1,
    const float* __restrict__ W2, const float* __restrict__ b2,
    const float* __restrict__ W3, const float* __restrict__ b3,
    const float* __restrict__ R1, const float* __restrict__ rb1,
    const float* __restrict__ R2, const float* __restrict__ rb2,
    float* __restrict__ out, int n)
{
    extern __shared__ float smem[];
    const int tid = threadIdx.x;
    const int lane = tid & 31;

    // ---- stage B = W2 bf16 hi/lo in mma-fragment pack ----
    // float4 at [(kc*16+nb)*32 + l]: for t=l&3, g=l>>2, n=8nb+g, k0=16kc+2t:
    //   .x = pack_trunc(W2[k0][n],  W2[k0+1][n])   (b_hi0)
    //   .y = pack_trunc(W2[k0+8][n],W2[k0+9][n])   (b_hi1)
    //   .z/.w = bf16_rn residual pairs             (b_lo0, b_lo1)
    for (int idx = tid; idx < 4096; idx += blockDim.x) {
        int l = idx & 31, nb = (idx >> 5) & 15, kc = idx >> 9;
        int t = l & 3, g = l >> 2;
        int nn = nb * 8 + g;
        int k0 = kc * 16 + 2 * t;
        float w00 = W2[k0 * HN + nn];
        float w01 = W2[(k0 + 1) * HN + nn];
        float w08 = W2[(k0 + 8) * HN + nn];
        float w09 = W2[(k0 + 9) * HN + nn];
        float4 v;
        v.x = __uint_as_float(pack_trunc(w00, w01));
        v.y = __uint_as_float(pack_trunc(w08, w09));
        v.z = __uint_as_float(pack_rn(w00 - trunc_bf16_f(w00), w01 - trunc_bf16_f(w01)));
        v.w = __uint_as_float(pack_rn(w08 - trunc_bf16_f(w08), w09 - trunc_bf16_f(w09)));
        reinterpret_cast<float4*>(smem + OFF_B)[idx] = v;
    }
    // ---- small weights ----
    {
        float4* w1v  = reinterpret_cast<float4*>(smem + OFF_W1);
        float2* bwv2 = reinterpret_cast<float2*>(smem + OFF_BW);
        float4* r1av = reinterpret_cast<float4*>(smem + OFF_R1A);
        float4* r1bv = reinterpret_cast<float4*>(smem + OFF_R1B);
        float4* r2v  = reinterpret_cast<float4*>(smem + OFF_R2);
        for (int j = tid; j < HN; j += blockDim.x) {
            w1v[j]  = make_float4(W1[j], W1[HN + j], W1[2 * HN + j], b1[j]);
            bwv2[j] = make_float2(b2[j], W3[j]);
            r1av[j] = make_float4(R1[j], R1[HN + j], R1[2 * HN + j], R1[3 * HN + j]);
            r1bv[j] = make_float4(R1[4 * HN + j], R1[5 * HN + j], rb1[j], 0.0f);
            r2v[j]  = make_float4(R2[3 * j], R2[3 * j + 1], R2[3 * j + 2], 0.0f);
        }
    }
    if (tid < 3) smem[OFF_MISC + tid] = rb2[tid];
    if (tid == 0) smem[OFF_MISC + 3] = b3[0];
    __syncthreads();

    const float4* w1pack = reinterpret_cast<const float4*>(smem + OFF_W1);
    const float4* sB4    = reinterpret_cast<const float4*>(smem + OFF_B);
    const float4* bwv    = reinterpret_cast<const float4*>(smem + OFF_BW);
    const float bb3 = smem[OFF_MISC + 3];

    int ray = blockIdx.x * blockDim.x + tid;
    const bool active = ray < n;
    if (!active) ray = n - 1;
    const float ro0 = rays[ray * 6 + 0], ro1 = rays[ray * 6 + 1], ro2 = rays[ray * 6 + 2];
    const float rd0 = rays[ray * 6 + 3], rd1 = rays[ray * 6 + 4], rd2 = rays[ray * 6 + 5];

    // ============ sphere tracing (warp-wide early break) ============
    float cd = kNEAR;
    bool hit = false;
#pragma unroll 1
    for (int it = 0; it < kITERS; ++it) {
        float x0 = __fadd_rn(ro0, __fmul_rn(rd0, cd));
        float x1 = __fadd_rn(ro1, __fmul_rn(rd1, cd));
        float x2 = __fadd_rn(ro2, __fmul_rn(rd2, cd));
        float X0[4], X1[4], X2[4];
        bcast_X(x0, x1, x2, lane, X0, X1, X2);
        float dist = sdf_eval_warp(X0, X1, X2, w1pack, sB4, bwv, lane) + bb3;
        bool h = (dist < kEPS) && (cd >= kNEAR) && (cd <= kFAR);
        hit = hit || h;
        if (!hit) cd += dist;
        if (__all_sync(0xffffffffu, hit)) break;
    }

    // ============ reflectance MLP (scalar, cheap) ============
    float p0 = __fadd_rn(ro0, __fmul_rn(rd0, cd));
    float p1 = __fadd_rn(ro1, __fmul_rn(rd1, cd));
    float p2 = __fadd_rn(ro2, __fmul_rn(rd2, cd));
    float rgb0 = smem[OFF_MISC + 0], rgb1 = smem[OFF_MISC + 1], rgb2 = smem[OFF_MISC + 2];
    {
        const float4* r1a = reinterpret_cast<const float4*>(smem + OFF_R1A);
        const float4* r1b = reinterpret_cast<const float4*>(smem + OFF_R1B);
        const float4* r2v = reinterpret_cast<const float4*>(smem + OFF_R2);
#pragma unroll 4
        for (int j = 0; j < HN; ++j) {
            float4 a = r1a[j];
            float4 b = r1b[j];
            float hv = fmaf(a.x, p0, fmaf(a.y, p1, fmaf(a.z, p2,
                       fmaf(a.w, rd0, fmaf(b.x, rd1, fmaf(b.y, rd2, b.z))))));
            hv = fmaxf(hv, 0.0f);
            float4 w = r2v[j];
            rgb0 = fmaf(hv, w.x, rgb0);
            rgb1 = fmaf(hv, w.y, rgb1);
            rgb2 = fmaf(hv, w.z, rgb2);
        }
    }
    if (!hit) { rgb0 = 0.0f; rgb1 = 0.0f; rgb2 = 0.0f; }

    // ============ tube-point min; tput == curr_min ============
    float m;
    {   // i = 0: point is exactly ro
        float X0[4], X1[4], X2[4];
        bcast_X(ro0, ro1, ro2, lane, X0, X1, X2);
        m = sdf_eval_warp(X0, X1, X2, w1pack, sB4, bwv, lane) + bb3;
    }
#pragma unroll 1
    for (int i = 1; i <= kTP; ++i) {
        float t = kSTEP * (float)i;  // == reference step*(i+1)
        float x0 = __fadd_rn(ro0, __fmul_rn(rd0, t));
        float x1 = __fadd_rn(ro1, __fmul_rn(rd1, t));
        float x2 = __fadd_rn(ro2, __fmul_rn(rd2, t));
        float X0[4], X1[4], X2[4];
        bcast_X(x0, x1, x2, lane, X0, X1, X2);
        float sd = sdf_eval_warp(X0, X1, X2, w1pack, sB4, bwv, lane) + bb3;
        m = fminf(m, sd);
    }

    if (active) {
        float4 o;
        o.x = rgb0; o.y = rgb1; o.z = rgb2; o.w = -kALPHA * m;
        reinterpret_cast<float4*>(out)[ray] = o;
    }
}

extern "C" void kernel_launch(void* const* d_in, const int* in_sizes, int n_in,
                              void* d_out, int out_size) {
    const float* rays = (const float*)d_in[0];
    const float* W1   = (const float*)d_in[1];
    const float* b1   = (const float*)d_in[2];
    const float* W2   = (const float*)d_in[3];
    const float* b2   = (const float*)d_in[4];
    const float* W3   = (const float*)d_in[5];
    const float* b3   = (const float*)d_in[6];
    const float* R1   = (const float*)d_in[7];
    const float* rb1  = (const float*)d_in[8];
    const float* R2   = (const float*)d_in[9];
    const float* rb2  = (const float*)d_in[10];
    float* out = (float*)d_out;

    const int n = in_sizes[0] / 6;

    cudaFuncSetAttribute(sdf_mma_kernel,
                         cudaFuncAttributeMaxDynamicSharedMemorySize, SMEM_BYTES);

    const int block = 256;
    const int grid = (n + block - 1) / block;
    sdf_mma_kernel<<<grid, block, SMEM_BYTES>>>(
        rays, W1, b1, W2, b2, W3, b3, R1, rb1, R2, rb2, out, n);
}

// round 8
// speedup vs baseline: 6.5496x; 1.3854x over previous
#include <cuda_runtime.h>
#include <cuda_fp16.h>
#include <cstdint>

// ---------------------------------------------------------------------------
// Neural-SDF ray march + tube min + reflectance.
// Warp-cooperative: 32 rays/warp; each SDF eval = 32x128x128 GEMM via
// mma.sync.m16n8k16 f16.
//   * march + tube scan: 1-term rounded-fp16 (err ~3e-4) -> 256 mma/eval
//   * column-3 value: ONE precise eval per ray at the approx-argmin point,
//     fp16 3-term (Ahi*Bhi + Alo*Bhi + Ahi*Blo, err ~2^-22).
//     Bound: result in [min_exact, min_exact + 2*eps_scan].
//   * A (h1) computed directly in mma fragment layout (never staged in SMEM)
//   * tput == curr_min identity removes a second full pass
// ---------------------------------------------------------------------------

#define DINL __device__ __forceinline__

namespace {
constexpr int   HN     = 128;
constexpr float kNEAR  = 0.2f;
constexpr float kFAR   = 2.0f;
constexpr float kALPHA = 100.0f;
constexpr float kEPS   = 0.005f;
constexpr int   kITERS = 32;
constexpr int   kTP    = 32;
constexpr float kSTEP  = 0.0634765625f;  // (2 + 0.5*(2/32))/32, exact fp32

// shared memory layout (float offsets)
constexpr int OFF_BH   = 0;        // 8192 floats: W2 fp16-hi frag pack (float2/entry)
constexpr int OFF_BL   = 8192;     // 8192 floats: W2 fp16-lo residual pack
constexpr int OFF_W1   = 16384;    // float4[128]: (W1[0][k],W1[1][k],W1[2][k],b1[k])
constexpr int OFF_BW   = 16896;    // float2[128]: (b2[n], W3[n])
constexpr int OFF_R1A  = 17152;    // float4[128]: R1 rows 0..3
constexpr int OFF_R1B  = 17664;    // float4[128]: (R1[4][j],R1[5][j],rb1[j],0)
constexpr int OFF_R2   = 18176;    // float4[128]: (R2[j][0..2],0)
constexpr int OFF_MISC = 18688;    // rb2[0..2], b3
constexpr int SMEM_FLOATS = 18692;
constexpr int SMEM_BYTES  = SMEM_FLOATS * 4;
}  // namespace

// ----------------------------- helpers --------------------------------------
// fp16 rn pack: low half = rn(e0), high half = rn(e1)
DINL uint32_t pk16(float e0, float e1) {
    uint32_t d;
    asm("cvt.rn.f16x2.f32 %0, %1, %2;" : "=r"(d) : "f"(e1), "f"(e0));
    return d;
}
DINL float f16_round(float x) { return __half2float(__float2half_rn(x)); }

// ----------------------------- mma wrappers ---------------------------------
DINL void mma16_acc(float c[4], uint32_t a0, uint32_t a1, uint32_t a2,
                    uint32_t a3, uint32_t b0, uint32_t b1) {
    asm volatile(
        "mma.sync.aligned.m16n8k16.row.col.f32.f16.f16.f32 "
        "{%0,%1,%2,%3},{%4,%5,%6,%7},{%8,%9},{%0,%1,%2,%3};"
        : "+f"(c[0]), "+f"(c[1]), "+f"(c[2]), "+f"(c[3])
        : "r"(a0), "r"(a1), "r"(a2), "r"(a3), "r"(b0), "r"(b1));
}
DINL void mma16_zero(float c[4], uint32_t a0, uint32_t a1, uint32_t a2,
                     uint32_t a3, uint32_t b0, uint32_t b1) {
    float z = 0.0f;
    asm volatile(
        "mma.sync.aligned.m16n8k16.row.col.f32.f16.f16.f32 "
        "{%0,%1,%2,%3},{%4,%5,%6,%7},{%8,%9},{%10,%10,%10,%10};"
        : "=f"(c[0]), "=f"(c[1]), "=f"(c[2]), "=f"(c[3])
        : "r"(a0), "r"(a1), "r"(a2), "r"(a3), "r"(b0), "r"(b1), "f"(z));
}

// ------------------- layer-1 in fragment layout ------------------------------
// k16-chunk kc: lane owns k = 16kc+2t{,+1,+8,+9}; rays X[c] = (lane>>2)+8c.
// Per m-tile mt (rays g+16mt, g+8+16mt):
//   a0={row g: k0,k0+1} a1={row g+8: k0,k0+1} a2={row g: k0+8,k0+9} a3={row g+8:...}
DINL void l1_vals(int kc, int t4, const float* X0, const float* X1,
                  const float* X2, const float4* __restrict__ w1pack,
                  float h[4][4]) {
    const int k0 = kc * 16 + 2 * t4;
    float4 w0 = w1pack[k0];
    float4 w1 = w1pack[k0 + 1];
    float4 w8 = w1pack[k0 + 8];
    float4 w9 = w1pack[k0 + 9];
#pragma unroll
    for (int c = 0; c < 4; ++c) {
        h[0][c] = fmaxf(fmaf(w0.x, X0[c], fmaf(w0.y, X1[c], fmaf(w0.z, X2[c], w0.w))), 0.0f);
        h[1][c] = fmaxf(fmaf(w1.x, X0[c], fmaf(w1.y, X1[c], fmaf(w1.z, X2[c], w1.w))), 0.0f);
        h[2][c] = fmaxf(fmaf(w8.x, X0[c], fmaf(w8.y, X1[c], fmaf(w8.z, X2[c], w8.w))), 0.0f);
        h[3][c] = fmaxf(fmaf(w9.x, X0[c], fmaf(w9.y, X1[c], fmaf(w9.z, X2[c], w9.w))), 0.0f);
    }
}
DINL void pack_A(const float h[4][4], uint32_t a[8]) {
#pragma unroll
    for (int mt = 0; mt < 2; ++mt) {
        const int cA = 2 * mt, cB = 2 * mt + 1;
        a[mt * 4 + 0] = pk16(h[0][cA], h[1][cA]);
        a[mt * 4 + 1] = pk16(h[0][cB], h[1][cB]);
        a[mt * 4 + 2] = pk16(h[2][cA], h[3][cA]);
        a[mt * 4 + 3] = pk16(h[2][cB], h[3][cB]);
    }
}

// --------------------------- epilogue ----------------------------------------
// p[r] = sum_n relu(C(r,n)+b2[n])*W3[n]; return own-ray value (WITHOUT b3)
DINL float reduce_out(const float C[2][16][4], const float4* __restrict__ bwv,
                      int lane) {
    const int t4 = lane & 3;
    float p0 = 0.f, p1 = 0.f, p2 = 0.f, p3 = 0.f;
#pragma unroll
    for (int nb = 0; nb < 16; ++nb) {
        float4 bw = bwv[nb * 4 + t4];  // (b2[n],W3[n],b2[n+1],W3[n+1]), n=8nb+2t
        p0 = fmaf(fmaxf(C[0][nb][0] + bw.x, 0.f), bw.y, p0);
        p0 = fmaf(fmaxf(C[0][nb][1] + bw.z, 0.f), bw.w, p0);
        p1 = fmaf(fmaxf(C[0][nb][2] + bw.x, 0.f), bw.y, p1);
        p1 = fmaf(fmaxf(C[0][nb][3] + bw.z, 0.f), bw.w, p1);
        p2 = fmaf(fmaxf(C[1][nb][0] + bw.x, 0.f), bw.y, p2);
        p2 = fmaf(fmaxf(C[1][nb][1] + bw.z, 0.f), bw.w, p2);
        p3 = fmaf(fmaxf(C[1][nb][2] + bw.x, 0.f), bw.y, p3);
        p3 = fmaf(fmaxf(C[1][nb][3] + bw.z, 0.f), bw.w, p3);
    }
    p0 += __shfl_xor_sync(0xffffffffu, p0, 1);
    p0 += __shfl_xor_sync(0xffffffffu, p0, 2);
    p1 += __shfl_xor_sync(0xffffffffu, p1, 1);
    p1 += __shfl_xor_sync(0xffffffffu, p1, 2);
    p2 += __shfl_xor_sync(0xffffffffu, p2, 1);
    p2 += __shfl_xor_sync(0xffffffffu, p2, 2);
    p3 += __shfl_xor_sync(0xffffffffu, p3, 1);
    p3 += __shfl_xor_sync(0xffffffffu, p3, 2);
    // lane 4g+c exposes ray g+8c; owner lane l fetches from 4*(l&7)+(l>>3)
    float expose = (t4 == 0) ? p0 : (t4 == 1) ? p1 : (t4 == 2) ? p2 : p3;
    int src = ((lane & 7) << 2) | (lane >> 3);
    return __shfl_sync(0xffffffffu, expose, src);
}

// --------------------- approx eval: 1-term fp16 (256 mma) --------------------
DINL float sdf_approx(const float* X0, const float* X1, const float* X2,
                      const float4* __restrict__ w1pack,
                      const float2* __restrict__ sBH,
                      const float4* __restrict__ bwv, int lane) {
    const int t4 = lane & 3;
    float C[2][16][4];
    const float2* bp = sBH + lane;
#pragma unroll 1
    for (int kc = 0; kc < 8; ++kc) {
        float h[4][4];
        uint32_t a[8];
        l1_vals(kc, t4, X0, X1, X2, w1pack, h);
        pack_A(h, a);
        const float2* bk = bp + kc * 512;
#pragma unroll
        for (int nb = 0; nb < 16; ++nb) {
            float2 B = bk[nb * 32];
            uint32_t b0 = __float_as_uint(B.x), b1 = __float_as_uint(B.y);
            if (kc == 0) {
                mma16_zero(C[0][nb], a[0], a[1], a[2], a[3], b0, b1);
                mma16_zero(C[1][nb], a[4], a[5], a[6], a[7], b0, b1);
            } else {
                mma16_acc(C[0][nb], a[0], a[1], a[2], a[3], b0, b1);
                mma16_acc(C[1][nb], a[4], a[5], a[6], a[7], b0, b1);
            }
        }
    }
    return reduce_out(C, bwv, lane);
}

// --------------- precise eval: 3-term fp16 (768 mma, err ~2^-22) -------------
DINL float sdf_precise(const float* X0, const float* X1, const float* X2,
                       const float4* __restrict__ w1pack,
                       const float2* __restrict__ sBH,
                       const float2* __restrict__ sBL,
                       const float4* __restrict__ bwv, int lane) {
    const int t4 = lane & 3;
    float C[2][16][4];
    const float2* bph = sBH + lane;
    const float2* bpl = sBL + lane;
#pragma unroll 1
    for (int kc = 0; kc < 8; ++kc) {
        float h[4][4], r[4][4];
        uint32_t ahi[8], alo[8];
        l1_vals(kc, t4, X0, X1, X2, w1pack, h);
#pragma unroll
        for (int s = 0; s < 4; ++s)
#pragma unroll
            for (int c = 0; c < 4; ++c) r[s][c] = h[s][c] - f16_round(h[s][c]);
        pack_A(h, ahi);
        pack_A(r, alo);
        const float2* bkh = bph + kc * 512;
        const float2* bkl = bpl + kc * 512;
#pragma unroll
        for (int nb = 0; nb < 16; ++nb) {
            float2 BH = bkh[nb * 32];
            float2 BL = bkl[nb * 32];
            uint32_t bh0 = __float_as_uint(BH.x), bh1 = __float_as_uint(BH.y);
            uint32_t bl0 = __float_as_uint(BL.x), bl1 = __float_as_uint(BL.y);
            if (kc == 0) {
                mma16_zero(C[0][nb], ahi[0], ahi[1], ahi[2], ahi[3], bh0, bh1);
                mma16_zero(C[1][nb], ahi[4], ahi[5], ahi[6], ahi[7], bh0, bh1);
            } else {
                mma16_acc(C[0][nb], ahi[0], ahi[1], ahi[2], ahi[3], bh0, bh1);
                mma16_acc(C[1][nb], ahi[4], ahi[5], ahi[6], ahi[7], bh0, bh1);
            }
            mma16_acc(C[0][nb], alo[0], alo[1], alo[2], alo[3], bh0, bh1);
            mma16_acc(C[1][nb], alo[4], alo[5], alo[6], alo[7], bh0, bh1);
            mma16_acc(C[0][nb], ahi[0], ahi[1], ahi[2], ahi[3], bl0, bl1);
            mma16_acc(C[1][nb], ahi[4], ahi[5], ahi[6], ahi[7], bl0, bl1);
        }
    }
    return reduce_out(C, bwv, lane);
}

DINL void bcast_X(float x0, float x1, float x2, int lane,
                  float* X0, float* X1, float* X2) {
#pragma unroll
    for (int c = 0; c < 4; ++c) {
        int src = (lane >> 2) + 8 * c;
        X0[c] = __shfl_sync(0xffffffffu, x0, src);
        X1[c] = __shfl_sync(0xffffffffu, x1, src);
        X2[c] = __shfl_sync(0xffffffffu, x2, src);
    }
}

// ------------------------------- kernel -------------------------------------
__global__ void __launch_bounds__(256, 1) sdf_mma_kernel(
    const float* __restrict__ rays,
    const float* __restrict__ W1, const float* __restrict__ b1,
    const float* __restrict__ W2, const float* __restrict__ b2,
    const float* __restrict__ W3, const float* __restrict__ b3,
    const float* __restrict__ R1, const float* __restrict__ rb1,
    const float* __restrict__ R2, const float* __restrict__ rb2,
    float* __restrict__ out, int n)
{
    extern __shared__ float smem[];
    const int tid = threadIdx.x;
    const int lane = tid & 31;

    // ---- stage B = W2 fp16 hi/lo in mma-fragment pack ----
    // entry [(kc*16+nb)*32 + l]: t=l&3, g=l>>2, n=8nb+g, k0=16kc+2t:
    //   BH = (pk16(W2[k0][n],W2[k0+1][n]), pk16(W2[k0+8][n],W2[k0+9][n]))
    //   BL = same for residuals W2 - f16(W2)
    for (int idx = tid; idx < 4096; idx += blockDim.x) {
        int l = idx & 31, nb = (idx >> 5) & 15, kc = idx >> 9;
        int t = l & 3, g = l >> 2;
        int nn = nb * 8 + g;
        int k0 = kc * 16 + 2 * t;
        float w00 = W2[k0 * HN + nn];
        float w01 = W2[(k0 + 1) * HN + nn];
        float w08 = W2[(k0 + 8) * HN + nn];
        float w09 = W2[(k0 + 9) * HN + nn];
        float2 bh, bl;
        bh.x = __uint_as_float(pk16(w00, w01));
        bh.y = __uint_as_float(pk16(w08, w09));
        bl.x = __uint_as_float(pk16(w00 - f16_round(w00), w01 - f16_round(w01)));
        bl.y = __uint_as_float(pk16(w08 - f16_round(w08), w09 - f16_round(w09)));
        reinterpret_cast<float2*>(smem + OFF_BH)[idx] = bh;
        reinterpret_cast<float2*>(smem + OFF_BL)[idx] = bl;
    }
    // ---- small weights ----
    {
        float4* w1v  = reinterpret_cast<float4*>(smem + OFF_W1);
        float2* bwv2 = reinterpret_cast<float2*>(smem + OFF_BW);
        float4* r1av = reinterpret_cast<float4*>(smem + OFF_R1A);
        float4* r1bv = reinterpret_cast<float4*>(smem + OFF_R1B);
        float4* r2v  = reinterpret_cast<float4*>(smem + OFF_R2);
        for (int j = tid; j < HN; j += blockDim.x) {
            w1v[j]  = make_float4(W1[j], W1[HN + j], W1[2 * HN + j], b1[j]);
            bwv2[j] = make_float2(b2[j], W3[j]);
            r1av[j] = make_float4(R1[j], R1[HN + j], R1[2 * HN + j], R1[3 * HN + j]);
            r1bv[j] = make_float4(R1[4 * HN + j], R1[5 * HN + j], rb1[j], 0.0f);
            r2v[j]  = make_float4(R2[3 * j], R2[3 * j + 1], R2[3 * j + 2], 0.0f);
        }
    }
    if (tid < 3) smem[OFF_MISC + tid] = rb2[tid];
    if (tid == 0) smem[OFF_MISC + 3] = b3[0];
    __syncthreads();

    const float4* w1pack = reinterpret_cast<const float4*>(smem + OFF_W1);
    const float2* sBH    = reinterpret_cast<const float2*>(smem + OFF_BH);
    const float2* sBL    = reinterpret_cast<const float2*>(smem + OFF_BL);
    const float4* bwv    = reinterpret_cast<const float4*>(smem + OFF_BW);
    const float bb3 = smem[OFF_MISC + 3];

    int ray = blockIdx.x * blockDim.x + tid;
    const bool active = ray < n;
    if (!active) ray = n - 1;
    const float ro0 = rays[ray * 6 + 0], ro1 = rays[ray * 6 + 1], ro2 = rays[ray * 6 + 2];
    const float rd0 = rays[ray * 6 + 3], rd1 = rays[ray * 6 + 4], rd2 = rays[ray * 6 + 5];

    // ============ sphere tracing (warp-wide early break) ============
    float cd = kNEAR;
    bool hit = false;
#pragma unroll 1
    for (int it = 0; it < kITERS; ++it) {
        float x0 = __fadd_rn(ro0, __fmul_rn(rd0, cd));
        float x1 = __fadd_rn(ro1, __fmul_rn(rd1, cd));
        float x2 = __fadd_rn(ro2, __fmul_rn(rd2, cd));
        float X0[4], X1[4], X2[4];
        bcast_X(x0, x1, x2, lane, X0, X1, X2);
        float dist = sdf_approx(X0, X1, X2, w1pack, sBH, bwv, lane) + bb3;
        bool h = (dist < kEPS) && (cd >= kNEAR) && (cd <= kFAR);
        hit = hit || h;
        if (!hit) cd += dist;
        if (__all_sync(0xffffffffu, hit)) break;
    }

    // ============ reflectance MLP (scalar, cheap) ============
    float p0 = __fadd_rn(ro0, __fmul_rn(rd0, cd));
    float p1 = __fadd_rn(ro1, __fmul_rn(rd1, cd));
    float p2 = __fadd_rn(ro2, __fmul_rn(rd2, cd));
    float rgb0 = smem[OFF_MISC + 0], rgb1 = smem[OFF_MISC + 1], rgb2 = smem[OFF_MISC + 2];
    {
        const float4* r1a = reinterpret_cast<const float4*>(smem + OFF_R1A);
        const float4* r1b = reinterpret_cast<const float4*>(smem + OFF_R1B);
        const float4* r2v = reinterpret_cast<const float4*>(smem + OFF_R2);
#pragma unroll 4
        for (int j = 0; j < HN; ++j) {
            float4 a = r1a[j];
            float4 b = r1b[j];
            float hv = fmaf(a.x, p0, fmaf(a.y, p1, fmaf(a.z, p2,
                       fmaf(a.w, rd0, fmaf(b.x, rd1, fmaf(b.y, rd2, b.z))))));
            hv = fmaxf(hv, 0.0f);
            float4 w = r2v[j];
            rgb0 = fmaf(hv, w.x, rgb0);
            rgb1 = fmaf(hv, w.y, rgb1);
            rgb2 = fmaf(hv, w.z, rgb2);
        }
    }
    if (!hit) { rgb0 = 0.0f; rgb1 = 0.0f; rgb2 = 0.0f; }

    // ============ tube-point scan (approx ranking) ============
    float m_ap = __int_as_float(0x7f800000);
    int   bi   = 0;
#pragma unroll 1
    for (int i = 0; i <= kTP; ++i) {
        float t = kSTEP * (float)i;
        float x0 = __fadd_rn(ro0, __fmul_rn(rd0, t));
        float x1 = __fadd_rn(ro1, __fmul_rn(rd1, t));
        float x2 = __fadd_rn(ro2, __fmul_rn(rd2, t));
        float X0[4], X1[4], X2[4];
        bcast_X(x0, x1, x2, lane, X0, X1, X2);
        float sd = sdf_approx(X0, X1, X2, w1pack, sBH, bwv, lane);
        if (sd < m_ap) { m_ap = sd; bi = i; }
    }
    // precise re-eval at the per-ray argmin point (tput == curr_min identity)
    float m;
    {
        float tb = kSTEP * (float)bi;
        float x0 = __fadd_rn(ro0, __fmul_rn(rd0, tb));
        float x1 = __fadd_rn(ro1, __fmul_rn(rd1, tb));
        float x2 = __fadd_rn(ro2, __fmul_rn(rd2, tb));
        float X0[4], X1[4], X2[4];
        bcast_X(x0, x1, x2, lane, X0, X1, X2);
        m = sdf_precise(X0, X1, X2, w1pack, sBH, sBL, bwv, lane) + bb3;
    }

    if (active) {
        float4 o;
        o.x = rgb0; o.y = rgb1; o.z = rgb2; o.w = -kALPHA * m;
        reinterpret_cast<float4*>(out)[ray] = o;
    }
}

extern "C" void kernel_launch(void* const* d_in, const int* in_sizes, int n_in,
                              void* d_out, int out_size) {
    const float* rays = (const float*)d_in[0];
    const float* W1   = (const float*)d_in[1];
    const float* b1   = (const float*)d_in[2];
    const float* W2   = (const float*)d_in[3];
    const float* b2   = (const float*)d_in[4];
    const float* W3   = (const float*)d_in[5];
    const float* b3   = (const float*)d_in[6];
    const float* R1   = (const float*)d_in[7];
    const float* rb1  = (const float*)d_in[8];
    const float* R2   = (const float*)d_in[9];
    const float* rb2  = (const float*)d_in[10];
    float* out = (float*)d_out;

    const int n = in_sizes[0] / 6;

    cudaFuncSetAttribute(sdf_mma_kernel,
                         cudaFuncAttributeMaxDynamicSharedMemorySize, SMEM_BYTES);

    const int block = 256;
    const int grid = (n + block - 1) / block;
    sdf_mma_kernel<<<grid, block, SMEM_BYTES>>>(
        rays, W1, b1, W2, b2, W3, b3, R1, rb1, R2, rb2, out, n);
}

// round 9
// speedup vs baseline: 10.8899x; 1.6627x over previous
#include <cuda_runtime.h>
#include <cuda_fp16.h>
#include <cstdint>

// ---------------------------------------------------------------------------
// Neural-SDF ray march + tube min + reflectance.
// Warp-cooperative: 32 rays/warp; each SDF eval = 32x128x128 GEMM via
// mma.sync.m16n8k16 f16.
//   * march + tube scan: 1-term fp16 (256 mma/eval)
//   * column-3: ONE precise fp16 3-term eval per ray at the approx argmin
//   * A-hi held in regs; layer-2 split into two n-halves (C 64 regs live)
//   * __launch_bounds__(128,3): 12 warps/SM to keep the tensor pipe fed
// ---------------------------------------------------------------------------

#define DINL __device__ __forceinline__

namespace {
constexpr int   HN     = 128;
constexpr float kNEAR  = 0.2f;
constexpr float kFAR   = 2.0f;
constexpr float kALPHA = 100.0f;
constexpr float kEPS   = 0.005f;
constexpr int   kITERS = 32;
constexpr int   kTP    = 32;
constexpr float kSTEP  = 0.0634765625f;  // (2 + 0.5*(2/32))/32, exact fp32

// shared memory layout (float offsets)
constexpr int OFF_BH   = 0;        // 8192 floats: W2 fp16-hi, float4 = 2 n-blocks
constexpr int OFF_BL   = 8192;     // 8192 floats: W2 fp16-lo residual, same layout
constexpr int OFF_W1   = 16384;    // float4[128]: (W1[0][k],W1[1][k],W1[2][k],b1[k])
constexpr int OFF_BW   = 16896;    // float2[128]: (b2[n], W3[n])
constexpr int OFF_R1A  = 17152;    // float4[128]: R1 rows 0..3
constexpr int OFF_R1B  = 17664;    // float4[128]: (R1[4][j],R1[5][j],rb1[j],0)
constexpr int OFF_R2   = 18176;    // float4[128]: (R2[j][0..2],0)
constexpr int OFF_MISC = 18688;    // rb2[0..2], b3
constexpr int SMEM_FLOATS = 18692;
constexpr int SMEM_BYTES  = SMEM_FLOATS * 4;
}  // namespace

// ----------------------------- helpers --------------------------------------
DINL uint32_t pk16(float e0, float e1) {   // low = rn(e0), high = rn(e1)
    uint32_t d;
    asm("cvt.rn.f16x2.f32 %0, %1, %2;" : "=r"(d) : "f"(e1), "f"(e0));
    return d;
}
DINL uint32_t pk16relu(float e0, float e1) {  // rn then clamp at 0
    uint32_t d;
    asm("cvt.rn.relu.f16x2.f32 %0, %1, %2;" : "=r"(d) : "f"(e1), "f"(e0));
    return d;
}
DINL float f16_round(float x) { return __half2float(__float2half_rn(x)); }

// ----------------------------- mma wrappers ---------------------------------
DINL void mma16_acc(float c[4], uint32_t a0, uint32_t a1, uint32_t a2,
                    uint32_t a3, uint32_t b0, uint32_t b1) {
    asm volatile(
        "mma.sync.aligned.m16n8k16.row.col.f32.f16.f16.f32 "
        "{%0,%1,%2,%3},{%4,%5,%6,%7},{%8,%9},{%0,%1,%2,%3};"
        : "+f"(c[0]), "+f"(c[1]), "+f"(c[2]), "+f"(c[3])
        : "r"(a0), "r"(a1), "r"(a2), "r"(a3), "r"(b0), "r"(b1));
}
DINL void mma16_zero(float c[4], uint32_t a0, uint32_t a1, uint32_t a2,
                     uint32_t a3, uint32_t b0, uint32_t b1) {
    float z = 0.0f;
    asm volatile(
        "mma.sync.aligned.m16n8k16.row.col.f32.f16.f16.f32 "
        "{%0,%1,%2,%3},{%4,%5,%6,%7},{%8,%9},{%10,%10,%10,%10};"
        : "=f"(c[0]), "=f"(c[1]), "=f"(c[2]), "=f"(c[3])
        : "r"(a0), "r"(a1), "r"(a2), "r"(a3), "r"(b0), "r"(b1), "f"(z));
}

// --------------------------- epilogue reduce ---------------------------------
// lane 4g+c exposes ray g+8c; owner lane l fetches from 4*(l&7)+(l>>3)
DINL float expose_own(float p0, float p1, float p2, float p3, int lane) {
    p0 += __shfl_xor_sync(0xffffffffu, p0, 1);
    p0 += __shfl_xor_sync(0xffffffffu, p0, 2);
    p1 += __shfl_xor_sync(0xffffffffu, p1, 1);
    p1 += __shfl_xor_sync(0xffffffffu, p1, 2);
    p2 += __shfl_xor_sync(0xffffffffu, p2, 1);
    p2 += __shfl_xor_sync(0xffffffffu, p2, 2);
    p3 += __shfl_xor_sync(0xffffffffu, p3, 1);
    p3 += __shfl_xor_sync(0xffffffffu, p3, 2);
    const int t4 = lane & 3;
    float expose = (t4 == 0) ? p0 : (t4 == 1) ? p1 : (t4 == 2) ? p2 : p3;
    int src = ((lane & 7) << 2) | (lane >> 3);
    return __shfl_sync(0xffffffffu, expose, src);
}

// --------------------- approx eval: 1-term fp16 (256 mma) --------------------
// X*[c] = coords of warp-ray (lane>>2)+8c. Returns own-ray value (WITHOUT b3).
DINL float sdf_approx(const float* X0, const float* X1, const float* X2,
                      const float4* __restrict__ w1pack,
                      const float4* __restrict__ sBH,
                      const float4* __restrict__ bwv, int lane) {
    const int t4 = lane & 3;

    // ---- layer-1: pack A_hi for all kc (relu fused into cvt) ----
    uint32_t Ah[64];
#pragma unroll
    for (int kc = 0; kc < 8; ++kc) {
        const int k0 = kc * 16 + 2 * t4;
        float4 w0 = w1pack[k0];
        float4 w1 = w1pack[k0 + 1];
        float4 w8 = w1pack[k0 + 8];
        float4 w9 = w1pack[k0 + 9];
#pragma unroll
        for (int mt = 0; mt < 2; ++mt) {
            const int cA = 2 * mt, cB = 2 * mt + 1;
            float h0A = fmaf(w0.x, X0[cA], fmaf(w0.y, X1[cA], fmaf(w0.z, X2[cA], w0.w)));
            float h1A = fmaf(w1.x, X0[cA], fmaf(w1.y, X1[cA], fmaf(w1.z, X2[cA], w1.w)));
            float h8A = fmaf(w8.x, X0[cA], fmaf(w8.y, X1[cA], fmaf(w8.z, X2[cA], w8.w)));
            float h9A = fmaf(w9.x, X0[cA], fmaf(w9.y, X1[cA], fmaf(w9.z, X2[cA], w9.w)));
            float h0B = fmaf(w0.x, X0[cB], fmaf(w0.y, X1[cB], fmaf(w0.z, X2[cB], w0.w)));
            float h1B = fmaf(w1.x, X0[cB], fmaf(w1.y, X1[cB], fmaf(w1.z, X2[cB], w1.w)));
            float h8B = fmaf(w8.x, X0[cB], fmaf(w8.y, X1[cB], fmaf(w8.z, X2[cB], w8.w)));
            float h9B = fmaf(w9.x, X0[cB], fmaf(w9.y, X1[cB], fmaf(w9.z, X2[cB], w9.w)));
            Ah[kc * 8 + mt * 4 + 0] = pk16relu(h0A, h1A);
            Ah[kc * 8 + mt * 4 + 1] = pk16relu(h0B, h1B);
            Ah[kc * 8 + mt * 4 + 2] = pk16relu(h8A, h9A);
            Ah[kc * 8 + mt * 4 + 3] = pk16relu(h8B, h9B);
        }
    }

    // ---- layer-2 + epilogue in two n-halves (C = 64 regs live) ----
    float p0 = 0.f, p1 = 0.f, p2 = 0.f, p3 = 0.f;
#pragma unroll
    for (int half = 0; half < 2; ++half) {
        float C[2][8][4];
#pragma unroll
        for (int kc = 0; kc < 8; ++kc) {
            const uint32_t* a = Ah + kc * 8;
            const float4* bq = sBH + (kc * 8 + half * 4) * 32 + lane;
#pragma unroll
            for (int nbp = 0; nbp < 4; ++nbp) {
                float4 B = bq[nbp * 32];
                uint32_t b0 = __float_as_uint(B.x), b1 = __float_as_uint(B.y);
                uint32_t b2r = __float_as_uint(B.z), b3r = __float_as_uint(B.w);
                if (kc == 0) {
                    mma16_zero(C[0][2 * nbp],     a[0], a[1], a[2], a[3], b0, b1);
                    mma16_zero(C[1][2 * nbp],     a[4], a[5], a[6], a[7], b0, b1);
                    mma16_zero(C[0][2 * nbp + 1], a[0], a[1], a[2], a[3], b2r, b3r);
                    mma16_zero(C[1][2 * nbp + 1], a[4], a[5], a[6], a[7], b2r, b3r);
                } else {
                    mma16_acc(C[0][2 * nbp],     a[0], a[1], a[2], a[3], b0, b1);
                    mma16_acc(C[1][2 * nbp],     a[4], a[5], a[6], a[7], b0, b1);
                    mma16_acc(C[0][2 * nbp + 1], a[0], a[1], a[2], a[3], b2r, b3r);
                    mma16_acc(C[1][2 * nbp + 1], a[4], a[5], a[6], a[7], b2r, b3r);
                }
            }
        }
#pragma unroll
        for (int nb = 0; nb < 8; ++nb) {
            float4 bw = bwv[(half * 8 + nb) * 4 + t4];
            p0 = fmaf(fmaxf(C[0][nb][0] + bw.x, 0.f), bw.y, p0);
            p0 = fmaf(fmaxf(C[0][nb][1] + bw.z, 0.f), bw.w, p0);
            p1 = fmaf(fmaxf(C[0][nb][2] + bw.x, 0.f), bw.y, p1);
            p1 = fmaf(fmaxf(C[0][nb][3] + bw.z, 0.f), bw.w, p1);
            p2 = fmaf(fmaxf(C[1][nb][0] + bw.x, 0.f), bw.y, p2);
            p2 = fmaf(fmaxf(C[1][nb][1] + bw.z, 0.f), bw.w, p2);
            p3 = fmaf(fmaxf(C[1][nb][2] + bw.x, 0.f), bw.y, p3);
            p3 = fmaf(fmaxf(C[1][nb][3] + bw.z, 0.f), bw.w, p3);
        }
    }
    return expose_own(p0, p1, p2, p3, lane);
}

// --------------- precise eval: 3-term fp16 (768 mma, once per ray) -----------
DINL float sdf_precise(const float* X0, const float* X1, const float* X2,
                       const float4* __restrict__ w1pack,
                       const float4* __restrict__ sBH,
                       const float4* __restrict__ sBL,
                       const float4* __restrict__ bwv, int lane) {
    const int t4 = lane & 3;
    float p0 = 0.f, p1 = 0.f, p2 = 0.f, p3 = 0.f;
#pragma unroll 1
    for (int half = 0; half < 2; ++half) {
        float C[2][8][4];
#pragma unroll 1
        for (int kc = 0; kc < 8; ++kc) {
            // layer-1 recomputed per half (once per ray total: cheap)
            const int k0 = kc * 16 + 2 * t4;
            float4 w0 = w1pack[k0];
            float4 w1 = w1pack[k0 + 1];
            float4 w8 = w1pack[k0 + 8];
            float4 w9 = w1pack[k0 + 9];
            uint32_t ahi[8], alo[8];
#pragma unroll
            for (int mt = 0; mt < 2; ++mt) {
                const int cA = 2 * mt, cB = 2 * mt + 1;
                float h[4][2];
                h[0][0] = fmaxf(fmaf(w0.x, X0[cA], fmaf(w0.y, X1[cA], fmaf(w0.z, X2[cA], w0.w))), 0.f);
                h[1][0] = fmaxf(fmaf(w1.x, X0[cA], fmaf(w1.y, X1[cA], fmaf(w1.z, X2[cA], w1.w))), 0.f);
                h[2][0] = fmaxf(fmaf(w8.x, X0[cA], fmaf(w8.y, X1[cA], fmaf(w8.z, X2[cA], w8.w))), 0.f);
                h[3][0] = fmaxf(fmaf(w9.x, X0[cA], fmaf(w9.y, X1[cA], fmaf(w9.z, X2[cA], w9.w))), 0.f);
                h[0][1] = fmaxf(fmaf(w0.x, X0[cB], fmaf(w0.y, X1[cB], fmaf(w0.z, X2[cB], w0.w))), 0.f);
                h[1][1] = fmaxf(fmaf(w1.x, X0[cB], fmaf(w1.y, X1[cB], fmaf(w1.z, X2[cB], w1.w))), 0.f);
                h[2][1] = fmaxf(fmaf(w8.x, X0[cB], fmaf(w8.y, X1[cB], fmaf(w8.z, X2[cB], w8.w))), 0.f);
                h[3][1] = fmaxf(fmaf(w9.x, X0[cB], fmaf(w9.y, X1[cB], fmaf(w9.z, X2[cB], w9.w))), 0.f);
                float r[4][2];
#pragma unroll
                for (int s = 0; s < 4; ++s) {
                    r[s][0] = h[s][0] - f16_round(h[s][0]);
                    r[s][1] = h[s][1] - f16_round(h[s][1]);
                }
                ahi[mt * 4 + 0] = pk16(h[0][0], h[1][0]);
                ahi[mt * 4 + 1] = pk16(h[0][1], h[1][1]);
                ahi[mt * 4 + 2] = pk16(h[2][0], h[3][0]);
                ahi[mt * 4 + 3] = pk16(h[2][1], h[3][1]);
                alo[mt * 4 + 0] = pk16(r[0][0], r[1][0]);
                alo[mt * 4 + 1] = pk16(r[0][1], r[1][1]);
                alo[mt * 4 + 2] = pk16(r[2][0], r[3][0]);
                alo[mt * 4 + 3] = pk16(r[2][1], r[3][1]);
            }
            const float4* bqh = sBH + (kc * 8 + half * 4) * 32 + lane;
            const float4* bql = sBL + (kc * 8 + half * 4) * 32 + lane;
#pragma unroll
            for (int nbp = 0; nbp < 4; ++nbp) {
                float4 BH = bqh[nbp * 32];
                float4 BL = bql[nbp * 32];
                uint32_t h0 = __float_as_uint(BH.x), h1 = __float_as_uint(BH.y);
                uint32_t h2 = __float_as_uint(BH.z), h3 = __float_as_uint(BH.w);
                uint32_t l0 = __float_as_uint(BL.x), l1 = __float_as_uint(BL.y);
                uint32_t l2 = __float_as_uint(BL.z), l3 = __float_as_uint(BL.w);
                if (kc == 0) {
                    mma16_zero(C[0][2 * nbp],     ahi[0], ahi[1], ahi[2], ahi[3], h0, h1);
                    mma16_zero(C[1][2 * nbp],     ahi[4], ahi[5], ahi[6], ahi[7], h0, h1);
                    mma16_zero(C[0][2 * nbp + 1], ahi[0], ahi[1], ahi[2], ahi[3], h2, h3);
                    mma16_zero(C[1][2 * nbp + 1], ahi[4], ahi[5], ahi[6], ahi[7], h2, h3);
                } else {
                    mma16_acc(C[0][2 * nbp],     ahi[0], ahi[1], ahi[2], ahi[3], h0, h1);
                    mma16_acc(C[1][2 * nbp],     ahi[4], ahi[5], ahi[6], ahi[7], h0, h1);
                    mma16_acc(C[0][2 * nbp + 1], ahi[0], ahi[1], ahi[2], ahi[3], h2, h3);
                    mma16_acc(C[1][2 * nbp + 1], ahi[4], ahi[5], ahi[6], ahi[7], h2, h3);
                }
                mma16_acc(C[0][2 * nbp],     alo[0], alo[1], alo[2], alo[3], h0, h1);
                mma16_acc(C[1][2 * nbp],     alo[4], alo[5], alo[6], alo[7], h0, h1);
                mma16_acc(C[0][2 * nbp + 1], alo[0], alo[1], alo[2], alo[3], h2, h3);
                mma16_acc(C[1][2 * nbp + 1], alo[4], alo[5], alo[6], alo[7], h2, h3);
                mma16_acc(C[0][2 * nbp],     ahi[0], ahi[1], ahi[2], ahi[3], l0, l1);
                mma16_acc(C[1][2 * nbp],     ahi[4], ahi[5], ahi[6], ahi[7], l0, l1);
                mma16_acc(C[0][2 * nbp + 1], ahi[0], ahi[1], ahi[2], ahi[3], l2, l3);
                mma16_acc(C[1][2 * nbp + 1], ahi[4], ahi[5], ahi[6], ahi[7], l2, l3);
            }
        }
#pragma unroll
        for (int nb = 0; nb < 8; ++nb) {
            float4 bw = bwv[(half * 8 + nb) * 4 + t4];
            p0 = fmaf(fmaxf(C[0][nb][0] + bw.x, 0.f), bw.y, p0);
            p0 = fmaf(fmaxf(C[0][nb][1] + bw.z, 0.f), bw.w, p0);
            p1 = fmaf(fmaxf(C[0][nb][2] + bw.x, 0.f), bw.y, p1);
            p1 = fmaf(fmaxf(C[0][nb][3] + bw.z, 0.f), bw.w, p1);
            p2 = fmaf(fmaxf(C[1][nb][0] + bw.x, 0.f), bw.y, p2);
            p2 = fmaf(fmaxf(C[1][nb][1] + bw.z, 0.f), bw.w, p2);
            p3 = fmaf(fmaxf(C[1][nb][2] + bw.x, 0.f), bw.y, p3);
            p3 = fmaf(fmaxf(C[1][nb][3] + bw.z, 0.f), bw.w, p3);
        }
    }
    return expose_own(p0, p1, p2, p3, lane);
}

DINL void bcast_X(float x0, float x1, float x2, int lane,
                  float* X0, float* X1, float* X2) {
#pragma unroll
    for (int c = 0; c < 4; ++c) {
        int src = (lane >> 2) + 8 * c;
        X0[c] = __shfl_sync(0xffffffffu, x0, src);
        X1[c] = __shfl_sync(0xffffffffu, x1, src);
        X2[c] = __shfl_sync(0xffffffffu, x2, src);
    }
}

// ------------------------------- kernel -------------------------------------
__global__ void __launch_bounds__(128, 3) sdf_mma_kernel(
    const float* __restrict__ rays,
    const float* __restrict__ W1, const float* __restrict__ b1,
    const float* __restrict__ W2, const float* __restrict__ b2,
    const float* __restrict__ W3, const float* __restrict__ b3,
    const float* __restrict__ R1, const float* __restrict__ rb1,
    const float* __restrict__ R2, const float* __restrict__ rb2,
    float* __restrict__ out, int n)
{
    extern __shared__ float smem[];
    const int tid = threadIdx.x;
    const int lane = tid & 31;

    // ---- stage B = W2 fp16 hi/lo, float4 covering 2 n-blocks per entry ----
    // entry idx: (kc*8 + nbp)*32 + l; t=l&3, g=l>>2, k0=16kc+2t,
    // n0=16nbp+g, n1=n0+8:
    //  BH = {pk(W2[k0][n0],W2[k0+1][n0]), pk(W2[k0+8][n0],W2[k0+9][n0]),
    //        pk(...n1...), pk(...n1...)}
    for (int idx = tid; idx < 2048; idx += blockDim.x) {
        int l = idx & 31, nbp = (idx >> 5) & 7, kc = idx >> 8;
        int t = l & 3, g = l >> 2;
        int n0 = nbp * 16 + g, n1 = n0 + 8;
        int k0 = kc * 16 + 2 * t;
        float a00 = W2[k0 * HN + n0],      a01 = W2[(k0 + 1) * HN + n0];
        float a08 = W2[(k0 + 8) * HN + n0], a09 = W2[(k0 + 9) * HN + n0];
        float b00 = W2[k0 * HN + n1],      b01 = W2[(k0 + 1) * HN + n1];
        float b08 = W2[(k0 + 8) * HN + n1], b09 = W2[(k0 + 9) * HN + n1];
        float4 vh, vl;
        vh.x = __uint_as_float(pk16(a00, a01));
        vh.y = __uint_as_float(pk16(a08, a09));
        vh.z = __uint_as_float(pk16(b00, b01));
        vh.w = __uint_as_float(pk16(b08, b09));
        vl.x = __uint_as_float(pk16(a00 - f16_round(a00), a01 - f16_round(a01)));
        vl.y = __uint_as_float(pk16(a08 - f16_round(a08), a09 - f16_round(a09)));
        vl.z = __uint_as_float(pk16(b00 - f16_round(b00), b01 - f16_round(b01)));
        vl.w = __uint_as_float(pk16(b08 - f16_round(b08), b09 - f16_round(b09)));
        reinterpret_cast<float4*>(smem + OFF_BH)[idx] = vh;
        reinterpret_cast<float4*>(smem + OFF_BL)[idx] = vl;
    }
    // ---- small weights ----
    {
        float4* w1v  = reinterpret_cast<float4*>(smem + OFF_W1);
        float2* bwv2 = reinterpret_cast<float2*>(smem + OFF_BW);
        float4* r1av = reinterpret_cast<float4*>(smem + OFF_R1A);
        float4* r1bv = reinterpret_cast<float4*>(smem + OFF_R1B);
        float4* r2v  = reinterpret_cast<float4*>(smem + OFF_R2);
        for (int j = tid; j < HN; j += blockDim.x) {
            w1v[j]  = make_float4(W1[j], W1[HN + j], W1[2 * HN + j], b1[j]);
            bwv2[j] = make_float2(b2[j], W3[j]);
            r1av[j] = make_float4(R1[j], R1[HN + j], R1[2 * HN + j], R1[3 * HN + j]);
            r1bv[j] = make_float4(R1[4 * HN + j], R1[5 * HN + j], rb1[j], 0.0f);
            r2v[j]  = make_float4(R2[3 * j], R2[3 * j + 1], R2[3 * j + 2], 0.0f);
        }
    }
    if (tid < 3) smem[OFF_MISC + tid] = rb2[tid];
    if (tid == 0) smem[OFF_MISC + 3] = b3[0];
    __syncthreads();

    const float4* w1pack = reinterpret_cast<const float4*>(smem + OFF_W1);
    const float4* sBH    = reinterpret_cast<const float4*>(smem + OFF_BH);
    const float4* sBL    = reinterpret_cast<const float4*>(smem + OFF_BL);
    const float4* bwv    = reinterpret_cast<const float4*>(smem + OFF_BW);
    const float bb3 = smem[OFF_MISC + 3];

    int ray = blockIdx.x * blockDim.x + tid;
    const bool active = ray < n;
    if (!active) ray = n - 1;
    const float ro0 = rays[ray * 6 + 0], ro1 = rays[ray * 6 + 1], ro2 = rays[ray * 6 + 2];
    const float rd0 = rays[ray * 6 + 3], rd1 = rays[ray * 6 + 4], rd2 = rays[ray * 6 + 5];

    // ============ sphere tracing (warp-wide early break) ============
    float cd = kNEAR;
    bool hit = false;
#pragma unroll 1
    for (int it = 0; it < kITERS; ++it) {
        float x0 = __fadd_rn(ro0, __fmul_rn(rd0, cd));
        float x1 = __fadd_rn(ro1, __fmul_rn(rd1, cd));
        float x2 = __fadd_rn(ro2, __fmul_rn(rd2, cd));
        float X0[4], X1[4], X2[4];
        bcast_X(x0, x1, x2, lane, X0, X1, X2);
        float dist = sdf_approx(X0, X1, X2, w1pack, sBH, bwv, lane) + bb3;
        bool h = (dist < kEPS) && (cd >= kNEAR) && (cd <= kFAR);
        hit = hit || h;
        if (!hit) cd += dist;
        if (__all_sync(0xffffffffu, hit)) break;
    }

    // ============ reflectance MLP (scalar, cheap) ============
    float p0 = __fadd_rn(ro0, __fmul_rn(rd0, cd));
    float p1 = __fadd_rn(ro1, __fmul_rn(rd1, cd));
    float p2 = __fadd_rn(ro2, __fmul_rn(rd2, cd));
    float rgb0 = smem[OFF_MISC + 0], rgb1 = smem[OFF_MISC + 1], rgb2 = smem[OFF_MISC + 2];
    {
        const float4* r1a = reinterpret_cast<const float4*>(smem + OFF_R1A);
        const float4* r1b = reinterpret_cast<const float4*>(smem + OFF_R1B);
        const float4* r2v = reinterpret_cast<const float4*>(smem + OFF_R2);
#pragma unroll 4
        for (int j = 0; j < HN; ++j) {
            float4 a = r1a[j];
            float4 b = r1b[j];
            float hv = fmaf(a.x, p0, fmaf(a.y, p1, fmaf(a.z, p2,
                       fmaf(a.w, rd0, fmaf(b.x, rd1, fmaf(b.y, rd2, b.z))))));
            hv = fmaxf(hv, 0.0f);
            float4 w = r2v[j];
            rgb0 = fmaf(hv, w.x, rgb0);
            rgb1 = fmaf(hv, w.y, rgb1);
            rgb2 = fmaf(hv, w.z, rgb2);
        }
    }
    if (!hit) { rgb0 = 0.0f; rgb1 = 0.0f; rgb2 = 0.0f; }

    // ============ tube-point scan (approx ranking) ============
    float m_ap = __int_as_float(0x7f800000);
    int   bi   = 0;
#pragma unroll 1
    for (int i = 0; i <= kTP; ++i) {
        float t = kSTEP * (float)i;
        float x0 = __fadd_rn(ro0, __fmul_rn(rd0, t));
        float x1 = __fadd_rn(ro1, __fmul_rn(rd1, t));
        float x2 = __fadd_rn(ro2, __fmul_rn(rd2, t));
        float X0[4], X1[4], X2[4];
        bcast_X(x0, x1, x2, lane, X0, X1, X2);
        float sd = sdf_approx(X0, X1, X2, w1pack, sBH, bwv, lane);
        if (sd < m_ap) { m_ap = sd; bi = i; }
    }
    // precise re-eval at the per-ray argmin point (tput == curr_min identity)
    float m;
    {
        float tb = kSTEP * (float)bi;
        float x0 = __fadd_rn(ro0, __fmul_rn(rd0, tb));
        float x1 = __fadd_rn(ro1, __fmul_rn(rd1, tb));
        float x2 = __fadd_rn(ro2, __fmul_rn(rd2, tb));
        float X0[4], X1[4], X2[4];
        bcast_X(x0, x1, x2, lane, X0, X1, X2);
        m = sdf_precise(X0, X1, X2, w1pack, sBH, sBL, bwv, lane) + bb3;
    }

    if (active) {
        float4 o;
        o.x = rgb0; o.y = rgb1; o.z = rgb2; o.w = -kALPHA * m;
        reinterpret_cast<float4*>(out)[ray] = o;
    }
}

extern "C" void kernel_launch(void* const* d_in, const int* in_sizes, int n_in,
                              void* d_out, int out_size) {
    const float* rays = (const float*)d_in[0];
    const float* W1   = (const float*)d_in[1];
    const float* b1   = (const float*)d_in[2];
    const float* W2   = (const float*)d_in[3];
    const float* b2   = (const float*)d_in[4];
    const float* W3   = (const float*)d_in[5];
    const float* b3   = (const float*)d_in[6];
    const float* R1   = (const float*)d_in[7];
    const float* rb1  = (const float*)d_in[8];
    const float* R2   = (const float*)d_in[9];
    const float* rb2  = (const float*)d_in[10];
    float* out = (float*)d_out;

    const int n = in_sizes[0] / 6;

    cudaFuncSetAttribute(sdf_mma_kernel,
                         cudaFuncAttributeMaxDynamicSharedMemorySize, SMEM_BYTES);

    const int block = 128;
    const int grid = (n + block - 1) / block;
    sdf_mma_kernel<<<grid, block, SMEM_BYTES>>>(
        rays, W1, b1, W2, b2, W3, b3, R1, rb1, R2, rb2, out, n);
}